// round 4
// baseline (speedup 1.0000x reference)
#include <cuda_runtime.h>

#define Bb  4
#define Ss  512
#define NHh 12
#define DHh 64
#define HID 768
#define ROWS (Bb*Ss)   // 2048

typedef unsigned long long ull;

// packed fp32x2 (Blackwell): one instruction = 2 fp32 ops on the fma pipe
#define PK2(dst, lo, hi)  asm("mov.b64 %0, {%1,%2};" : "=l"(dst) : "f"(lo), "f"(hi))
#define UPK2(lo, hi, src) asm("mov.b64 {%0,%1}, %2;" : "=f"(lo), "=f"(hi) : "l"(src))
#define FMA2(acc, a, b)   asm("fma.rn.f32x2 %0, %1, %2, %0;" : "+l"(acc) : "l"(a), "l"(b))
#define ADD2(d, a, b)     asm("add.rn.f32x2 %0, %1, %2;" : "=l"(d) : "l"(a), "l"(b))
#define MUL2(d, a, b)     asm("mul.rn.f32x2 %0, %1, %2;" : "=l"(d) : "l"(a), "l"(b))

// scratch (allocation-free rule: __device__ globals)
__device__ float g_q [ROWS*HID];          // [B,S,HID]
__device__ float g_kt[ROWS*HID];          // [B,NH,DH,S]  (transposed K)
__device__ float g_v [ROWS*HID];          // [B,S,HID]

// ---------------- QKV projection GEMM (FFMA2 mainloop) ----------------
#define BM 64
#define BN 64
#define BK 16

__global__ void __launch_bounds__(256) qkv_gemm(
    const float* __restrict__ A,
    const float* __restrict__ Wq, const float* __restrict__ bq,
    const float* __restrict__ Wk, const float* __restrict__ bk,
    const float* __restrict__ Wv, const float* __restrict__ bv)
{
    const int z = blockIdx.z;
    const float* W    = (z == 0) ? Wq : (z == 1) ? Wk : Wv;
    const float* bias = (z == 0) ? bq : (z == 1) ? bk : bv;

    __shared__ float As[BK][BM + 4];
    __shared__ float Ws[BK][BN];

    const int tid = threadIdx.x;
    const int rowBase = blockIdx.y * BM;
    const int colBase = blockIdx.x * BN;

    const int tm = (tid / 16) * 4;
    const int tn = (tid % 16) * 4;

    const int lm  = tid / 4;
    const int lk4 = (tid % 4) * 4;
    const int lwk = tid / 16;
    const int lwn = (tid % 16) * 4;

    // acc packed along m: accp[ipair][j] = {row tm+2*ipair, tm+2*ipair+1} col j
    ull accp[2][4] = {};

    for (int k0 = 0; k0 < HID; k0 += BK) {
        __syncthreads();
        float4 av = *(const float4*)&A[(rowBase + lm) * HID + k0 + lk4];
        As[lk4 + 0][lm] = av.x;
        As[lk4 + 1][lm] = av.y;
        As[lk4 + 2][lm] = av.z;
        As[lk4 + 3][lm] = av.w;
        *(float4*)&Ws[lwk][lwn] =
            *(const float4*)&W[(k0 + lwk) * HID + colBase + lwn];
        __syncthreads();

        #pragma unroll
        for (int k = 0; k < BK; k++) {
            float4 a = *(const float4*)&As[k][tm];
            float4 w = *(const float4*)&Ws[k][tn];
            ull a01, a23, w0d, w1d, w2d, w3d;
            PK2(a01, a.x, a.y);
            PK2(a23, a.z, a.w);
            PK2(w0d, w.x, w.x);
            PK2(w1d, w.y, w.y);
            PK2(w2d, w.z, w.z);
            PK2(w3d, w.w, w.w);
            FMA2(accp[0][0], a01, w0d); FMA2(accp[1][0], a23, w0d);
            FMA2(accp[0][1], a01, w1d); FMA2(accp[1][1], a23, w1d);
            FMA2(accp[0][2], a01, w2d); FMA2(accp[1][2], a23, w2d);
            FMA2(accp[0][3], a01, w3d); FMA2(accp[1][3], a23, w3d);
        }
    }

    float acc[4][4];
    #pragma unroll
    for (int j = 0; j < 4; j++) {
        UPK2(acc[0][j], acc[1][j], accp[0][j]);
        UPK2(acc[2][j], acc[3][j], accp[1][j]);
    }

    #pragma unroll
    for (int i = 0; i < 4; i++) {
        const int row = rowBase + tm + i;
        #pragma unroll
        for (int j = 0; j < 4; j++) {
            const int col = colBase + tn + j;
            const float c = acc[i][j] + bias[col];
            if (z == 0) {
                g_q[row * HID + col] = c;
            } else if (z == 2) {
                g_v[row * HID + col] = c;
            } else {
                const int b = row >> 9, s = row & 511;
                const int h = col >> 6, d = col & 63;
                g_kt[((b * NHh + h) * DHh + d) * Ss + s] = c;
            }
        }
    }
}

// ---------------- fused relational attention, v4 (FFMA2) ----------------
// CTA = 4 q-rows, all 12 heads, 384 threads = 12 warps.
// rel_s layout [k][d^(k&7)][qi] (16B-granule XOR swizzle): 4-phase
// conflict-free for lane=k (score) AND lane=d (ctx). qi innermost
// everywhere so float4 loads give free f32x2 register pairs.
#define TQ 4
#define TK 64

#define Q_OFF   (TK * DHh * TQ)               // 16384
#define SC_OFF  (Q_OFF + HID * TQ)            // +3072
#define ML_OFF  (SC_OFF + NHh * TK * TQ)      // +3072
#define SM_FLOATS (ML_OFF + 3 * TQ * NHh)     // +144
#define SM_BYTES  (SM_FLOATS * 4)             // 90,688

__global__ void __launch_bounds__(384) attn(
    const float* __restrict__ mask,   // [B,1,1,S]
    const float* __restrict__ rel,    // [B,S,S,DH]
    float* __restrict__ out)          // [B,S,HID]
{
    extern __shared__ float sm[];
    float* rel_s = sm;                  // [(k*64 + (d^(k&7)))*4 + qi]
    float* q_s   = sm + Q_OFF;          // [(h*64+d)*4 + qi], pre-scaled
    float* sc    = sm + SC_OFF;         // [(h*TK+k)*4 + qi]
    float* m_s   = sm + ML_OFF;         // [qi*12+h]
    float* l_s   = m_s + TQ * NHh;
    float* al_s  = l_s + TQ * NHh;

    const int cta  = blockIdx.x;          // 512
    const int b    = cta >> 7;
    const int q0   = (cta & 127) << 2;
    const int tid  = threadIdx.x;
    const int wid  = tid >> 5;
    const int lane = tid & 31;

    for (int i = tid; i < HID; i += 384) {
        #pragma unroll
        for (int qi = 0; qi < TQ; qi++)
            q_s[i * TQ + qi] = g_q[(b * Ss + q0 + qi) * HID + i] * 0.125f;
    }
    if (tid < TQ * NHh) { m_s[tid] = -1e30f; l_s[tid] = 0.f; }

    const int pw = wid % 6;
    const int gw = wid / 6;
    const int h0 = pw * 2, h1 = h0 + 1;

    ull c0p[2] = {0, 0}, c1p[2] = {0, 0};   // ctx packed {qi0,qi1},{qi2,qi3}

    for (int kb = 0; kb < Ss; kb += TK) {
        __syncthreads();
        // ---- stage rel: [qi][k][d] gmem -> swizzled [k][d'][qi] smem
        for (int i = tid; i < TQ * TK * 16; i += 384) {
            const int qi = i >> 10;
            const int r  = i & 1023;
            const int k  = r >> 4;
            const int d4 = (r & 15) << 2;
            const int kc = k & 7;
            float4 v = *(const float4*)&rel[
                (((long)(b * Ss + q0 + qi)) * Ss + kb + k) * DHh + d4];
            rel_s[(k * DHh + ((d4 + 0) ^ kc)) * TQ + qi] = v.x;
            rel_s[(k * DHh + ((d4 + 1) ^ kc)) * TQ + qi] = v.y;
            rel_s[(k * DHh + ((d4 + 2) ^ kc)) * TQ + qi] = v.z;
            rel_s[(k * DHh + ((d4 + 3) ^ kc)) * TQ + qi] = v.w;
        }
        __syncthreads();

        // ---- scores: lane = k; packed FMA2, batched K loads (MLP 8)
        {
            const int k  = (gw << 5) + lane;
            const int kc = k & 7;
            const float* kt0 = g_kt + ((b * NHh + h0) * DHh) * Ss + kb + k;
            const float* kt1 = kt0 + DHh * Ss;
            const float* rlk = &rel_s[k * DHh * TQ];
            ull a0p[2] = {0, 0}, a1p[2] = {0, 0};
            #pragma unroll
            for (int d0 = 0; d0 < DHh; d0 += 4) {
                float kv0[4], kv1[4];
                #pragma unroll
                for (int j = 0; j < 4; j++) {
                    kv0[j] = kt0[(d0 + j) * Ss];
                    kv1[j] = kt1[(d0 + j) * Ss];
                }
                #pragma unroll
                for (int j = 0; j < 4; j++) {
                    const int d = d0 + j;
                    float4 rr = *(const float4*)&rlk[(d ^ kc) * TQ];
                    float4 qa = *(const float4*)&q_s[(h0 * DHh + d) * TQ];
                    float4 qb = *(const float4*)&q_s[(h1 * DHh + d) * TQ];
                    ull rr01, rr23, qa01, qa23, qb01, qb23, k0d, k1d;
                    PK2(rr01, rr.x, rr.y); PK2(rr23, rr.z, rr.w);
                    PK2(qa01, qa.x, qa.y); PK2(qa23, qa.z, qa.w);
                    PK2(qb01, qb.x, qb.y); PK2(qb23, qb.z, qb.w);
                    PK2(k0d, kv0[j], kv0[j]);
                    PK2(k1d, kv1[j], kv1[j]);
                    FMA2(a0p[0], qa01, k0d);  FMA2(a0p[1], qa23, k0d);
                    FMA2(a0p[0], qa01, rr01); FMA2(a0p[1], qa23, rr23);
                    FMA2(a1p[0], qb01, k1d);  FMA2(a1p[1], qb23, k1d);
                    FMA2(a1p[0], qb01, rr01); FMA2(a1p[1], qb23, rr23);
                }
            }
            const float mv = mask[b * Ss + kb + k];
            float s0, s1, s2, s3, t0, t1, t2, t3;
            UPK2(s0, s1, a0p[0]); UPK2(s2, s3, a0p[1]);
            UPK2(t0, t1, a1p[0]); UPK2(t2, t3, a1p[1]);
            float4 w0 = {s0 + mv, s1 + mv, s2 + mv, s3 + mv};
            float4 w1 = {t0 + mv, t1 + mv, t2 + mv, t3 + mv};
            *(float4*)&sc[(h0 * TK + k) * TQ] = w0;
            *(float4*)&sc[(h1 * TK + k) * TQ] = w1;
        }
        __syncthreads();

        // ---- online softmax: warp = head, all 4 qi at once
        {
            const int h = wid;
            float4 x0 = *(const float4*)&sc[(h * TK + lane) * TQ];
            float4 x1 = *(const float4*)&sc[(h * TK + lane + 32) * TQ];
            float xa[4] = {x0.x, x0.y, x0.z, x0.w};
            float xb[4] = {x1.x, x1.y, x1.z, x1.w};
            float pa[4], pb[4], ls[4], mn[4];
            #pragma unroll
            for (int qi = 0; qi < TQ; qi++) {
                float mx = fmaxf(xa[qi], xb[qi]);
                #pragma unroll
                for (int o = 16; o; o >>= 1)
                    mx = fmaxf(mx, __shfl_xor_sync(0xffffffffu, mx, o));
                mn[qi] = fmaxf(m_s[qi * NHh + h], mx);
                pa[qi] = __expf(xa[qi] - mn[qi]);
                pb[qi] = __expf(xb[qi] - mn[qi]);
                float s = pa[qi] + pb[qi];
                #pragma unroll
                for (int o = 16; o; o >>= 1)
                    s += __shfl_xor_sync(0xffffffffu, s, o);
                ls[qi] = s;
            }
            float4 w0 = {pa[0], pa[1], pa[2], pa[3]};
            float4 w1 = {pb[0], pb[1], pb[2], pb[3]};
            *(float4*)&sc[(h * TK + lane) * TQ] = w0;
            *(float4*)&sc[(h * TK + lane + 32) * TQ] = w1;
            if (lane == 0) {
                #pragma unroll
                for (int qi = 0; qi < TQ; qi++) {
                    const float alpha = __expf(m_s[qi * NHh + h] - mn[qi]);
                    al_s[qi * NHh + h] = alpha;
                    l_s[qi * NHh + h]  = l_s[qi * NHh + h] * alpha + ls[qi];
                    m_s[qi * NHh + h]  = mn[qi];
                }
            }
        }
        __syncthreads();

        // ---- ctx: lane = d; packed FMA2, batched V loads (MLP 8)
        {
            const int d = (gw << 5) + lane;
            ull alA01, alA23, alB01, alB23;
            PK2(alA01, al_s[h0], al_s[NHh + h0]);
            PK2(alA23, al_s[2 * NHh + h0], al_s[3 * NHh + h0]);
            PK2(alB01, al_s[h1], al_s[NHh + h1]);
            PK2(alB23, al_s[2 * NHh + h1], al_s[3 * NHh + h1]);
            MUL2(c0p[0], c0p[0], alA01); MUL2(c0p[1], c0p[1], alA23);
            MUL2(c1p[0], c1p[0], alB01); MUL2(c1p[1], c1p[1], alB23);
            const float* vp = g_v + (long)(b * Ss + kb) * HID + d;
            #pragma unroll
            for (int k0 = 0; k0 < TK; k0 += 4) {
                float v0[4], v1[4];
                #pragma unroll
                for (int j = 0; j < 4; j++) {
                    v0[j] = vp[(k0 + j) * HID + h0 * DHh];
                    v1[j] = vp[(k0 + j) * HID + h1 * DHh];
                }
                #pragma unroll
                for (int j = 0; j < 4; j++) {
                    const int k  = k0 + j;
                    const int kc = k & 7;
                    float4 p0 = *(const float4*)&sc[(h0 * TK + k) * TQ];
                    float4 p1 = *(const float4*)&sc[(h1 * TK + k) * TQ];
                    float4 rr = *(const float4*)&rel_s[(k * DHh + (d ^ kc)) * TQ];
                    ull rr01, rr23, p001, p023, p101, p123, v0d, v1d;
                    ull t01, t23, u01, u23;
                    PK2(rr01, rr.x, rr.y); PK2(rr23, rr.z, rr.w);
                    PK2(p001, p0.x, p0.y); PK2(p023, p0.z, p0.w);
                    PK2(p101, p1.x, p1.y); PK2(p123, p1.z, p1.w);
                    PK2(v0d, v0[j], v0[j]);
                    PK2(v1d, v1[j], v1[j]);
                    ADD2(t01, v0d, rr01); ADD2(t23, v0d, rr23);
                    FMA2(c0p[0], p001, t01); FMA2(c0p[1], p023, t23);
                    ADD2(u01, v1d, rr01); ADD2(u23, v1d, rr23);
                    FMA2(c1p[0], p101, u01); FMA2(c1p[1], p123, u23);
                }
            }
        }
    }

    // ---- write out
    {
        const int d = (gw << 5) + lane;
        float c00, c01, c02, c03, c10, c11, c12, c13;
        UPK2(c00, c01, c0p[0]); UPK2(c02, c03, c0p[1]);
        UPK2(c10, c11, c1p[0]); UPK2(c12, c13, c1p[1]);
        float ca[4] = {c00, c01, c02, c03};
        float cb[4] = {c10, c11, c12, c13};
        #pragma unroll
        for (int qi = 0; qi < TQ; qi++) {
            out[(long)(b * Ss + q0 + qi) * HID + h0 * DHh + d] =
                ca[qi] / l_s[qi * NHh + h0];
            out[(long)(b * Ss + q0 + qi) * HID + h1 * DHh + d] =
                cb[qi] / l_s[qi * NHh + h1];
        }
    }
}

extern "C" void kernel_launch(void* const* d_in, const int* in_sizes, int n_in,
                              void* d_out, int out_size)
{
    const float* hidden = (const float*)d_in[0];
    const float* mask   = (const float*)d_in[1];
    const float* rel    = (const float*)d_in[2];
    const float* Wq     = (const float*)d_in[3];
    const float* bq     = (const float*)d_in[4];
    const float* Wk     = (const float*)d_in[5];
    const float* bk     = (const float*)d_in[6];
    const float* Wv     = (const float*)d_in[7];
    const float* bv     = (const float*)d_in[8];
    float* out = (float*)d_out;

    cudaFuncSetAttribute(attn, cudaFuncAttributeMaxDynamicSharedMemorySize, SM_BYTES);

    dim3 g(HID / BN, ROWS / BM, 3);
    qkv_gemm<<<g, 256>>>(hidden, Wq, bq, Wk, bk, Wv, bv);
    attn<<<ROWS / TQ, 384, SM_BYTES>>>(mask, rel, out);
}

// round 5
// speedup vs baseline: 1.0125x; 1.0125x over previous
#include <cuda_runtime.h>

#define Bb  4
#define Ss  512
#define NHh 12
#define DHh 64
#define HID 768
#define ROWS (Bb*Ss)   // 2048

typedef unsigned long long ull;

// packed fp32x2 (Blackwell): one instruction = 2 fp32 ops on the fma pipe
#define PK2(dst, lo, hi)  asm("mov.b64 %0, {%1,%2};" : "=l"(dst) : "f"(lo), "f"(hi))
#define UPK2(lo, hi, src) asm("mov.b64 {%0,%1}, %2;" : "=f"(lo), "=f"(hi) : "l"(src))
#define FMA2(acc, a, b)   asm("fma.rn.f32x2 %0, %1, %2, %0;" : "+l"(acc) : "l"(a), "l"(b))
#define ADD2(d, a, b)     asm("add.rn.f32x2 %0, %1, %2;" : "=l"(d) : "l"(a), "l"(b))
#define MUL2(d, a, b)     asm("mul.rn.f32x2 %0, %1, %2;" : "=l"(d) : "l"(a), "l"(b))

// scratch (allocation-free rule: __device__ globals)
__device__ float g_q [ROWS*HID];          // [B,S,HID]
__device__ float g_kt[ROWS*HID];          // [B,NH,DH,S]  (transposed K)
__device__ float g_v [ROWS*HID];          // [B,S,HID]

// ---------------- QKV projection GEMM (FFMA2 mainloop) ----------------
#define BM 64
#define BN 64
#define BK 16

__global__ void __launch_bounds__(256) qkv_gemm(
    const float* __restrict__ A,
    const float* __restrict__ Wq, const float* __restrict__ bq,
    const float* __restrict__ Wk, const float* __restrict__ bk,
    const float* __restrict__ Wv, const float* __restrict__ bv)
{
    const int z = blockIdx.z;
    const float* W    = (z == 0) ? Wq : (z == 1) ? Wk : Wv;
    const float* bias = (z == 0) ? bq : (z == 1) ? bk : bv;

    __shared__ float As[BK][BM + 4];
    __shared__ float Ws[BK][BN];

    const int tid = threadIdx.x;
    const int rowBase = blockIdx.y * BM;
    const int colBase = blockIdx.x * BN;

    const int tm = (tid / 16) * 4;
    const int tn = (tid % 16) * 4;

    const int lm  = tid / 4;
    const int lk4 = (tid % 4) * 4;
    const int lwk = tid / 16;
    const int lwn = (tid % 16) * 4;

    // acc packed along m: accp[ipair][j] = {row tm+2*ipair, tm+2*ipair+1} col j
    ull accp[2][4] = {};

    for (int k0 = 0; k0 < HID; k0 += BK) {
        __syncthreads();
        float4 av = *(const float4*)&A[(rowBase + lm) * HID + k0 + lk4];
        As[lk4 + 0][lm] = av.x;
        As[lk4 + 1][lm] = av.y;
        As[lk4 + 2][lm] = av.z;
        As[lk4 + 3][lm] = av.w;
        *(float4*)&Ws[lwk][lwn] =
            *(const float4*)&W[(k0 + lwk) * HID + colBase + lwn];
        __syncthreads();

        #pragma unroll
        for (int k = 0; k < BK; k++) {
            float4 a = *(const float4*)&As[k][tm];
            float4 w = *(const float4*)&Ws[k][tn];
            ull a01, a23, w0d, w1d, w2d, w3d;
            PK2(a01, a.x, a.y);
            PK2(a23, a.z, a.w);
            PK2(w0d, w.x, w.x);
            PK2(w1d, w.y, w.y);
            PK2(w2d, w.z, w.z);
            PK2(w3d, w.w, w.w);
            FMA2(accp[0][0], a01, w0d); FMA2(accp[1][0], a23, w0d);
            FMA2(accp[0][1], a01, w1d); FMA2(accp[1][1], a23, w1d);
            FMA2(accp[0][2], a01, w2d); FMA2(accp[1][2], a23, w2d);
            FMA2(accp[0][3], a01, w3d); FMA2(accp[1][3], a23, w3d);
        }
    }

    float acc[4][4];
    #pragma unroll
    for (int j = 0; j < 4; j++) {
        UPK2(acc[0][j], acc[1][j], accp[0][j]);
        UPK2(acc[2][j], acc[3][j], accp[1][j]);
    }

    #pragma unroll
    for (int i = 0; i < 4; i++) {
        const int row = rowBase + tm + i;
        #pragma unroll
        for (int j = 0; j < 4; j++) {
            const int col = colBase + tn + j;
            const float c = acc[i][j] + bias[col];
            if (z == 0) {
                g_q[row * HID + col] = c;
            } else if (z == 2) {
                g_v[row * HID + col] = c;
            } else {
                const int b = row >> 9, s = row & 511;
                const int h = col >> 6, d = col & 63;
                g_kt[((b * NHh + h) * DHh + d) * Ss + s] = c;
            }
        }
    }
}

// ---------------- fused relational attention, v4 (FFMA2) ----------------
// CTA = 4 q-rows, all 12 heads, 384 threads = 12 warps.
// rel_s layout [k][d^(k&7)][qi] (16B-granule XOR swizzle): 4-phase
// conflict-free for lane=k (score) AND lane=d (ctx). qi innermost
// everywhere so float4 loads give free f32x2 register pairs.
#define TQ 4
#define TK 64

#define Q_OFF   (TK * DHh * TQ)               // 16384
#define SC_OFF  (Q_OFF + HID * TQ)            // +3072
#define ML_OFF  (SC_OFF + NHh * TK * TQ)      // +3072
#define SM_FLOATS (ML_OFF + 3 * TQ * NHh)     // +144
#define SM_BYTES  (SM_FLOATS * 4)             // 90,688

__global__ void __launch_bounds__(384) attn(
    const float* __restrict__ mask,   // [B,1,1,S]
    const float* __restrict__ rel,    // [B,S,S,DH]
    float* __restrict__ out)          // [B,S,HID]
{
    extern __shared__ float sm[];
    float* rel_s = sm;                  // [(k*64 + (d^(k&7)))*4 + qi]
    float* q_s   = sm + Q_OFF;          // [(h*64+d)*4 + qi], pre-scaled
    float* sc    = sm + SC_OFF;         // [(h*TK+k)*4 + qi]
    float* m_s   = sm + ML_OFF;         // [qi*12+h]
    float* l_s   = m_s + TQ * NHh;
    float* al_s  = l_s + TQ * NHh;

    const int cta  = blockIdx.x;          // 512
    const int b    = cta >> 7;
    const int q0   = (cta & 127) << 2;
    const int tid  = threadIdx.x;
    const int wid  = tid >> 5;
    const int lane = tid & 31;

    for (int i = tid; i < HID; i += 384) {
        #pragma unroll
        for (int qi = 0; qi < TQ; qi++)
            q_s[i * TQ + qi] = g_q[(b * Ss + q0 + qi) * HID + i] * 0.125f;
    }
    if (tid < TQ * NHh) { m_s[tid] = -1e30f; l_s[tid] = 0.f; }

    const int pw = wid % 6;
    const int gw = wid / 6;
    const int h0 = pw * 2, h1 = h0 + 1;

    ull c0p[2] = {0, 0}, c1p[2] = {0, 0};   // ctx packed {qi0,qi1},{qi2,qi3}

    for (int kb = 0; kb < Ss; kb += TK) {
        __syncthreads();
        // ---- stage rel: [qi][k][d] gmem -> swizzled [k][d'][qi] smem
        for (int i = tid; i < TQ * TK * 16; i += 384) {
            const int qi = i >> 10;
            const int r  = i & 1023;
            const int k  = r >> 4;
            const int d4 = (r & 15) << 2;
            const int kc = k & 7;
            float4 v = *(const float4*)&rel[
                (((long)(b * Ss + q0 + qi)) * Ss + kb + k) * DHh + d4];
            rel_s[(k * DHh + ((d4 + 0) ^ kc)) * TQ + qi] = v.x;
            rel_s[(k * DHh + ((d4 + 1) ^ kc)) * TQ + qi] = v.y;
            rel_s[(k * DHh + ((d4 + 2) ^ kc)) * TQ + qi] = v.z;
            rel_s[(k * DHh + ((d4 + 3) ^ kc)) * TQ + qi] = v.w;
        }
        __syncthreads();

        // ---- scores: lane = k; packed FMA2, batched K loads (MLP 8)
        {
            const int k  = (gw << 5) + lane;
            const int kc = k & 7;
            const float* kt0 = g_kt + ((b * NHh + h0) * DHh) * Ss + kb + k;
            const float* kt1 = kt0 + DHh * Ss;
            const float* rlk = &rel_s[k * DHh * TQ];
            ull a0p[2] = {0, 0}, a1p[2] = {0, 0};
            #pragma unroll
            for (int d0 = 0; d0 < DHh; d0 += 4) {
                float kv0[4], kv1[4];
                #pragma unroll
                for (int j = 0; j < 4; j++) {
                    kv0[j] = kt0[(d0 + j) * Ss];
                    kv1[j] = kt1[(d0 + j) * Ss];
                }
                #pragma unroll
                for (int j = 0; j < 4; j++) {
                    const int d = d0 + j;
                    float4 rr = *(const float4*)&rlk[(d ^ kc) * TQ];
                    float4 qa = *(const float4*)&q_s[(h0 * DHh + d) * TQ];
                    float4 qb = *(const float4*)&q_s[(h1 * DHh + d) * TQ];
                    ull rr01, rr23, qa01, qa23, qb01, qb23, k0d, k1d;
                    PK2(rr01, rr.x, rr.y); PK2(rr23, rr.z, rr.w);
                    PK2(qa01, qa.x, qa.y); PK2(qa23, qa.z, qa.w);
                    PK2(qb01, qb.x, qb.y); PK2(qb23, qb.z, qb.w);
                    PK2(k0d, kv0[j], kv0[j]);
                    PK2(k1d, kv1[j], kv1[j]);
                    FMA2(a0p[0], qa01, k0d);  FMA2(a0p[1], qa23, k0d);
                    FMA2(a0p[0], qa01, rr01); FMA2(a0p[1], qa23, rr23);
                    FMA2(a1p[0], qb01, k1d);  FMA2(a1p[1], qb23, k1d);
                    FMA2(a1p[0], qb01, rr01); FMA2(a1p[1], qb23, rr23);
                }
            }
            const float mv = mask[b * Ss + kb + k];
            float s0, s1, s2, s3, t0, t1, t2, t3;
            UPK2(s0, s1, a0p[0]); UPK2(s2, s3, a0p[1]);
            UPK2(t0, t1, a1p[0]); UPK2(t2, t3, a1p[1]);
            float4 w0 = {s0 + mv, s1 + mv, s2 + mv, s3 + mv};
            float4 w1 = {t0 + mv, t1 + mv, t2 + mv, t3 + mv};
            *(float4*)&sc[(h0 * TK + k) * TQ] = w0;
            *(float4*)&sc[(h1 * TK + k) * TQ] = w1;
        }
        __syncthreads();

        // ---- online softmax: warp = head, all 4 qi at once
        {
            const int h = wid;
            float4 x0 = *(const float4*)&sc[(h * TK + lane) * TQ];
            float4 x1 = *(const float4*)&sc[(h * TK + lane + 32) * TQ];
            float xa[4] = {x0.x, x0.y, x0.z, x0.w};
            float xb[4] = {x1.x, x1.y, x1.z, x1.w};
            float pa[4], pb[4], ls[4], mn[4];
            #pragma unroll
            for (int qi = 0; qi < TQ; qi++) {
                float mx = fmaxf(xa[qi], xb[qi]);
                #pragma unroll
                for (int o = 16; o; o >>= 1)
                    mx = fmaxf(mx, __shfl_xor_sync(0xffffffffu, mx, o));
                mn[qi] = fmaxf(m_s[qi * NHh + h], mx);
                pa[qi] = __expf(xa[qi] - mn[qi]);
                pb[qi] = __expf(xb[qi] - mn[qi]);
                float s = pa[qi] + pb[qi];
                #pragma unroll
                for (int o = 16; o; o >>= 1)
                    s += __shfl_xor_sync(0xffffffffu, s, o);
                ls[qi] = s;
            }
            float4 w0 = {pa[0], pa[1], pa[2], pa[3]};
            float4 w1 = {pb[0], pb[1], pb[2], pb[3]};
            *(float4*)&sc[(h * TK + lane) * TQ] = w0;
            *(float4*)&sc[(h * TK + lane + 32) * TQ] = w1;
            if (lane == 0) {
                #pragma unroll
                for (int qi = 0; qi < TQ; qi++) {
                    const float alpha = __expf(m_s[qi * NHh + h] - mn[qi]);
                    al_s[qi * NHh + h] = alpha;
                    l_s[qi * NHh + h]  = l_s[qi * NHh + h] * alpha + ls[qi];
                    m_s[qi * NHh + h]  = mn[qi];
                }
            }
        }
        __syncthreads();

        // ---- ctx: lane = d; packed FMA2, batched V loads (MLP 8)
        {
            const int d = (gw << 5) + lane;
            ull alA01, alA23, alB01, alB23;
            PK2(alA01, al_s[h0], al_s[NHh + h0]);
            PK2(alA23, al_s[2 * NHh + h0], al_s[3 * NHh + h0]);
            PK2(alB01, al_s[h1], al_s[NHh + h1]);
            PK2(alB23, al_s[2 * NHh + h1], al_s[3 * NHh + h1]);
            MUL2(c0p[0], c0p[0], alA01); MUL2(c0p[1], c0p[1], alA23);
            MUL2(c1p[0], c1p[0], alB01); MUL2(c1p[1], c1p[1], alB23);
            const float* vp = g_v + (long)(b * Ss + kb) * HID + d;
            #pragma unroll
            for (int k0 = 0; k0 < TK; k0 += 4) {
                float v0[4], v1[4];
                #pragma unroll
                for (int j = 0; j < 4; j++) {
                    v0[j] = vp[(k0 + j) * HID + h0 * DHh];
                    v1[j] = vp[(k0 + j) * HID + h1 * DHh];
                }
                #pragma unroll
                for (int j = 0; j < 4; j++) {
                    const int k  = k0 + j;
                    const int kc = k & 7;
                    float4 p0 = *(const float4*)&sc[(h0 * TK + k) * TQ];
                    float4 p1 = *(const float4*)&sc[(h1 * TK + k) * TQ];
                    float4 rr = *(const float4*)&rel_s[(k * DHh + (d ^ kc)) * TQ];
                    ull rr01, rr23, p001, p023, p101, p123, v0d, v1d;
                    ull t01, t23, u01, u23;
                    PK2(rr01, rr.x, rr.y); PK2(rr23, rr.z, rr.w);
                    PK2(p001, p0.x, p0.y); PK2(p023, p0.z, p0.w);
                    PK2(p101, p1.x, p1.y); PK2(p123, p1.z, p1.w);
                    PK2(v0d, v0[j], v0[j]);
                    PK2(v1d, v1[j], v1[j]);
                    ADD2(t01, v0d, rr01); ADD2(t23, v0d, rr23);
                    FMA2(c0p[0], p001, t01); FMA2(c0p[1], p023, t23);
                    ADD2(u01, v1d, rr01); ADD2(u23, v1d, rr23);
                    FMA2(c1p[0], p101, u01); FMA2(c1p[1], p123, u23);
                }
            }
        }
    }

    // ---- write out
    {
        const int d = (gw << 5) + lane;
        float c00, c01, c02, c03, c10, c11, c12, c13;
        UPK2(c00, c01, c0p[0]); UPK2(c02, c03, c0p[1]);
        UPK2(c10, c11, c1p[0]); UPK2(c12, c13, c1p[1]);
        float ca[4] = {c00, c01, c02, c03};
        float cb[4] = {c10, c11, c12, c13};
        #pragma unroll
        for (int qi = 0; qi < TQ; qi++) {
            out[(long)(b * Ss + q0 + qi) * HID + h0 * DHh + d] =
                ca[qi] / l_s[qi * NHh + h0];
            out[(long)(b * Ss + q0 + qi) * HID + h1 * DHh + d] =
                cb[qi] / l_s[qi * NHh + h1];
        }
    }
}

extern "C" void kernel_launch(void* const* d_in, const int* in_sizes, int n_in,
                              void* d_out, int out_size)
{
    const float* hidden = (const float*)d_in[0];
    const float* mask   = (const float*)d_in[1];
    const float* rel    = (const float*)d_in[2];
    const float* Wq     = (const float*)d_in[3];
    const float* bq     = (const float*)d_in[4];
    const float* Wk     = (const float*)d_in[5];
    const float* bk     = (const float*)d_in[6];
    const float* Wv     = (const float*)d_in[7];
    const float* bv     = (const float*)d_in[8];
    float* out = (float*)d_out;

    cudaFuncSetAttribute(attn, cudaFuncAttributeMaxDynamicSharedMemorySize, SM_BYTES);

    dim3 g(HID / BN, ROWS / BM, 3);
    qkv_gemm<<<g, 256>>>(hidden, Wq, bq, Wk, bk, Wv, bv);
    attn<<<ROWS / TQ, 384, SM_BYTES>>>(mask, rel, out);
}

// round 6
// speedup vs baseline: 1.0464x; 1.0334x over previous
#include <cuda_runtime.h>

#define Bb  4
#define Ss  512
#define NHh 12
#define DHh 64
#define HID 768
#define ROWS (Bb*Ss)   // 2048

typedef unsigned long long ull;

// packed fp32x2 (Blackwell)
#define PK2(dst, lo, hi)  asm("mov.b64 %0, {%1,%2};" : "=l"(dst) : "f"(lo), "f"(hi))
#define UPK2(lo, hi, src) asm("mov.b64 {%0,%1}, %2;" : "=f"(lo), "=f"(hi) : "l"(src))
#define FMA2(acc, a, b)   asm("fma.rn.f32x2 %0, %1, %2, %0;" : "+l"(acc) : "l"(a), "l"(b))
#define ADD2(d, a, b)     asm("add.rn.f32x2 %0, %1, %2;" : "=l"(d) : "l"(a), "l"(b))
#define MUL2(d, a, b)     asm("mul.rn.f32x2 %0, %1, %2;" : "=l"(d) : "l"(a), "l"(b))

__device__ float g_q [ROWS*HID];          // [B,S,HID]
__device__ float g_kt[ROWS*HID];          // [B,NH,DH,S]
__device__ float g_v [ROWS*HID];          // [B,S,HID]

// ---------------- QKV GEMM: 128x128x8, 8x8/thread, prefetch -------------
#define GM 128
#define GN 128
#define GK 8

__global__ void __launch_bounds__(256, 2) qkv_gemm(
    const float* __restrict__ A,
    const float* __restrict__ Wq, const float* __restrict__ bq,
    const float* __restrict__ Wk, const float* __restrict__ bk,
    const float* __restrict__ Wv, const float* __restrict__ bv)
{
    const int z = blockIdx.z;
    const float* W    = (z == 0) ? Wq : (z == 1) ? Wk : Wv;
    const float* bias = (z == 0) ? bq : (z == 1) ? bk : bv;

    __shared__ float As[GK][GM + 4];
    __shared__ float Ws[GK][GN];

    const int tid = threadIdx.x;
    const int rowBase = blockIdx.y * GM;
    const int colBase = blockIdx.x * GN;

    const int arow = tid >> 1;            // 0..127
    const int ak   = (tid & 1) * 4;       // 0 or 4
    const int wk   = tid >> 5;            // 0..7
    const int wn   = (tid & 31) * 4;      // 0..124

    const int tx = tid & 15;              // col group
    const int ty = tid >> 4;              // row group

    float4 aF = *(const float4*)&A[(rowBase + arow) * HID + ak];
    float4 wF = *(const float4*)&W[wk * HID + colBase + wn];

    float acc[8][8] = {};

    for (int k0 = 0; k0 < HID; k0 += GK) {
        As[ak + 0][arow] = aF.x;
        As[ak + 1][arow] = aF.y;
        As[ak + 2][arow] = aF.z;
        As[ak + 3][arow] = aF.w;
        *(float4*)&Ws[wk][wn] = wF;
        __syncthreads();

        if (k0 + GK < HID) {
            aF = *(const float4*)&A[(rowBase + arow) * HID + k0 + GK + ak];
            wF = *(const float4*)&W[(k0 + GK + wk) * HID + colBase + wn];
        }

        #pragma unroll
        for (int k = 0; k < GK; k++) {
            float4 a0 = *(const float4*)&As[k][ty * 8];
            float4 a1 = *(const float4*)&As[k][ty * 8 + 4];
            float4 b0 = *(const float4*)&Ws[k][tx * 8];
            float4 b1 = *(const float4*)&Ws[k][tx * 8 + 4];
            const float av[8] = {a0.x, a0.y, a0.z, a0.w, a1.x, a1.y, a1.z, a1.w};
            const float bv2[8] = {b0.x, b0.y, b0.z, b0.w, b1.x, b1.y, b1.z, b1.w};
            #pragma unroll
            for (int i = 0; i < 8; i++)
                #pragma unroll
                for (int j = 0; j < 8; j++)
                    acc[i][j] += av[i] * bv2[j];
        }
        __syncthreads();
    }

    #pragma unroll
    for (int i = 0; i < 8; i++) {
        const int row = rowBase + ty * 8 + i;
        #pragma unroll
        for (int j = 0; j < 8; j++) {
            const int col = colBase + tx * 8 + j;
            const float c = acc[i][j] + bias[col];
            if (z == 0) {
                g_q[row * HID + col] = c;
            } else if (z == 2) {
                g_v[row * HID + col] = c;
            } else {
                const int b = row >> 9, s = row & 511;
                const int h = col >> 6, d = col & 63;
                g_kt[((b * NHh + h) * DHh + d) * Ss + s] = c;
            }
        }
    }
}

// ---------------- fused relational attention, v6 ----------------
// CTA = 4 q-rows, 384 threads = 12 warps, warp = head (h = wid).
// Per warp: scores, softmax (regs), probs, alpha, ctx — all same warp.
// ONE __syncthreads per k-block. rel double-buffered in SMEM; K/V loads
// software-pipelined. Layout [k][d^(k&7)][qi], qi innermost (FMA2 pairs).
#define TQ 4
#define TK 32
#define NBLK (Ss / TK)                    // 16

#define RELBUF (TK * DHh * TQ)            // 8192 floats
#define Q_OFF  (2 * RELBUF)               // 16384
#define SC_OFF (Q_OFF + HID * TQ)         // 19456
#define SM_FLOATS (SC_OFF + NHh * TK * TQ)  // 20992
#define SM_BYTES  (SM_FLOATS * 4)           // 83968

#define CHUNKS (TQ * TK * 16)             // 2048 float4 chunks per block

__global__ void __launch_bounds__(384, 2) attn(
    const float* __restrict__ mask,   // [B,1,1,S]
    const float* __restrict__ rel,    // [B,S,S,DH]
    float* __restrict__ out)          // [B,S,HID]
{
    extern __shared__ float sm[];
    float* q_s = sm + Q_OFF;            // [(h*64+d)*4 + qi], pre-scaled
    float* sc  = sm + SC_OFF;           // [(h*TK+k)*4 + qi]  probs

    const int cta  = blockIdx.x;        // 512
    const int b    = cta >> 7;
    const int q0   = (cta & 127) << 2;
    const int tid  = threadIdx.x;
    const int h    = tid >> 5;          // warp = head
    const int lane = tid & 31;

    // stage q (coalesced per qi row)
    for (int i = tid; i < HID; i += 384) {
        #pragma unroll
        for (int qi = 0; qi < TQ; qi++)
            q_s[i * TQ + qi] = g_q[(b * Ss + q0 + qi) * HID + i] * 0.125f;
    }

    // stage rel block 0 into buffer 0
    {
        float4 t[6];
        #pragma unroll
        for (int it = 0; it < 6; it++) {
            const int i = tid + it * 384;
            if (i < CHUNKS) {
                const int qi = i >> 9, r = i & 511, k = r >> 4, d4 = (r & 15) << 2;
                t[it] = *(const float4*)&rel[
                    (((long)(b * Ss + q0 + qi)) * Ss + k) * DHh + d4];
            }
        }
        #pragma unroll
        for (int it = 0; it < 6; it++) {
            const int i = tid + it * 384;
            if (i < CHUNKS) {
                const int qi = i >> 9, r = i & 511, k = r >> 4, d4 = (r & 15) << 2;
                const int kc = k & 7;
                sm[(k * DHh + ((d4 + 0) ^ kc)) * TQ + qi] = t[it].x;
                sm[(k * DHh + ((d4 + 1) ^ kc)) * TQ + qi] = t[it].y;
                sm[(k * DHh + ((d4 + 2) ^ kc)) * TQ + qi] = t[it].z;
                sm[(k * DHh + ((d4 + 3) ^ kc)) * TQ + qi] = t[it].w;
            }
        }
    }
    __syncthreads();

    float m[TQ], l[TQ];
    #pragma unroll
    for (int qi = 0; qi < TQ; qi++) { m[qi] = -1e30f; l[qi] = 0.f; }

    ull c0p[2] = {0, 0}, c1p[2] = {0, 0};   // ctx [d-half][qi-pair]

    const float* ktbase = g_kt + ((b * NHh + h) * DHh) * Ss;

    for (int blk = 0; blk < NBLK; blk++) {
        const int kb = blk * TK;
        const float* relc = sm + (blk & 1) * RELBUF;

        // ---- SCORE: lane = k; pipelined K loads
        const int k  = lane;
        const int kc = k & 7;
        const float* kt = ktbase + kb + k;
        ull a01 = 0, a23 = 0;
        {
            float kv[8];
            #pragma unroll
            for (int j = 0; j < 8; j++) kv[j] = kt[j * Ss];
            #pragma unroll
            for (int g = 0; g < 8; g++) {
                float nkv[8];
                if (g < 7) {
                    #pragma unroll
                    for (int j = 0; j < 8; j++) nkv[j] = kt[((g + 1) * 8 + j) * Ss];
                }
                #pragma unroll
                for (int j = 0; j < 8; j++) {
                    const int d = g * 8 + j;
                    float4 q4 = *(const float4*)&q_s[(h * DHh + d) * TQ];
                    float4 r4 = *(const float4*)&relc[(k * DHh + (d ^ kc)) * TQ];
                    ull q01, q23, r01, r23, kd, t01, t23;
                    PK2(q01, q4.x, q4.y); PK2(q23, q4.z, q4.w);
                    PK2(r01, r4.x, r4.y); PK2(r23, r4.z, r4.w);
                    PK2(kd, kv[j], kv[j]);
                    ADD2(t01, kd, r01);  ADD2(t23, kd, r23);
                    FMA2(a01, q01, t01); FMA2(a23, q23, t23);
                }
                if (g < 7) {
                    #pragma unroll
                    for (int j = 0; j < 8; j++) kv[j] = nkv[j];
                }
            }
        }

        // ---- softmax (all in registers, warp-local)
        float alpha[TQ], pa[TQ];
        {
            const float mv = mask[b * Ss + kb + k];
            float s[TQ];
            UPK2(s[0], s[1], a01); UPK2(s[2], s[3], a23);
            #pragma unroll
            for (int qi = 0; qi < TQ; qi++) {
                s[qi] += mv;
                float mx = s[qi];
                #pragma unroll
                for (int o = 16; o; o >>= 1)
                    mx = fmaxf(mx, __shfl_xor_sync(0xffffffffu, mx, o));
                const float mnew = fmaxf(m[qi], mx);
                const float p = __expf(s[qi] - mnew);
                float ls = p;
                #pragma unroll
                for (int o = 16; o; o >>= 1)
                    ls += __shfl_xor_sync(0xffffffffu, ls, o);
                alpha[qi] = __expf(m[qi] - mnew);
                l[qi] = l[qi] * alpha[qi] + ls;
                m[qi] = mnew;
                pa[qi] = p;
            }
            float4 pw = {pa[0], pa[1], pa[2], pa[3]};
            *(float4*)&sc[(h * TK + k) * TQ] = pw;
        }

        // ---- stage NEXT rel block into other buffer (hidden by other warps)
        if (blk + 1 < NBLK) {
            float* reln = sm + ((blk + 1) & 1) * RELBUF;
            const int kbn = kb + TK;
            float4 t[6];
            #pragma unroll
            for (int it = 0; it < 6; it++) {
                const int i = tid + it * 384;
                if (i < CHUNKS) {
                    const int qi = i >> 9, r = i & 511, kk = r >> 4, d4 = (r & 15) << 2;
                    t[it] = *(const float4*)&rel[
                        (((long)(b * Ss + q0 + qi)) * Ss + kbn + kk) * DHh + d4];
                }
            }
            #pragma unroll
            for (int it = 0; it < 6; it++) {
                const int i = tid + it * 384;
                if (i < CHUNKS) {
                    const int qi = i >> 9, r = i & 511, kk = r >> 4, d4 = (r & 15) << 2;
                    const int kc2 = kk & 7;
                    reln[(kk * DHh + ((d4 + 0) ^ kc2)) * TQ + qi] = t[it].x;
                    reln[(kk * DHh + ((d4 + 1) ^ kc2)) * TQ + qi] = t[it].y;
                    reln[(kk * DHh + ((d4 + 2) ^ kc2)) * TQ + qi] = t[it].z;
                    reln[(kk * DHh + ((d4 + 3) ^ kc2)) * TQ + qi] = t[it].w;
                }
            }
        }
        __syncwarp();

        // ---- CTX: lane = d (covers d and d+32); pipelined V loads
        {
            const int d = lane;
            ull al01, al23;
            PK2(al01, alpha[0], alpha[1]); PK2(al23, alpha[2], alpha[3]);
            MUL2(c0p[0], c0p[0], al01); MUL2(c0p[1], c0p[1], al23);
            MUL2(c1p[0], c1p[0], al01); MUL2(c1p[1], c1p[1], al23);

            const float* vp = g_v + (long)(b * Ss + kb) * HID + h * DHh + d;
            float vv[8];   // [j*2 + half] for group of 4 k
            #pragma unroll
            for (int j = 0; j < 4; j++) {
                vv[j * 2 + 0] = vp[j * HID];
                vv[j * 2 + 1] = vp[j * HID + 32];
            }
            #pragma unroll
            for (int g = 0; g < 8; g++) {
                float nv[8];
                if (g < 7) {
                    #pragma unroll
                    for (int j = 0; j < 4; j++) {
                        nv[j * 2 + 0] = vp[((g + 1) * 4 + j) * HID];
                        nv[j * 2 + 1] = vp[((g + 1) * 4 + j) * HID + 32];
                    }
                }
                #pragma unroll
                for (int j = 0; j < 4; j++) {
                    const int kk  = g * 4 + j;
                    const int kc2 = kk & 7;
                    float4 p4 = *(const float4*)&sc[(h * TK + kk) * TQ];
                    float4 rA = *(const float4*)&relc[(kk * DHh + (d ^ kc2)) * TQ];
                    float4 rB = *(const float4*)&relc[(kk * DHh + ((d + 32) ^ kc2)) * TQ];
                    ull p01, p23, rA01, rA23, rB01, rB23, vA, vB, t01, t23, u01, u23;
                    PK2(p01, p4.x, p4.y); PK2(p23, p4.z, p4.w);
                    PK2(rA01, rA.x, rA.y); PK2(rA23, rA.z, rA.w);
                    PK2(rB01, rB.x, rB.y); PK2(rB23, rB.z, rB.w);
                    PK2(vA, vv[j * 2 + 0], vv[j * 2 + 0]);
                    PK2(vB, vv[j * 2 + 1], vv[j * 2 + 1]);
                    ADD2(t01, vA, rA01); ADD2(t23, vA, rA23);
                    FMA2(c0p[0], p01, t01); FMA2(c0p[1], p23, t23);
                    ADD2(u01, vB, rB01); ADD2(u23, vB, rB23);
                    FMA2(c1p[0], p01, u01); FMA2(c1p[1], p23, u23);
                }
                if (g < 7) {
                    #pragma unroll
                    for (int j = 0; j < 8; j++) vv[j] = nv[j];
                }
            }
        }
        __syncthreads();   // rel next buffer fully staged; cur readers done
    }

    // ---- write out
    {
        const int d = lane;
        float ca[TQ], cb[TQ];
        UPK2(ca[0], ca[1], c0p[0]); UPK2(ca[2], ca[3], c0p[1]);
        UPK2(cb[0], cb[1], c1p[0]); UPK2(cb[2], cb[3], c1p[1]);
        #pragma unroll
        for (int qi = 0; qi < TQ; qi++) {
            const long rowoff = (long)(b * Ss + q0 + qi) * HID + h * DHh;
            out[rowoff + d]      = ca[qi] / l[qi];
            out[rowoff + d + 32] = cb[qi] / l[qi];
        }
    }
}

extern "C" void kernel_launch(void* const* d_in, const int* in_sizes, int n_in,
                              void* d_out, int out_size)
{
    const float* hidden = (const float*)d_in[0];
    const float* mask   = (const float*)d_in[1];
    const float* rel    = (const float*)d_in[2];
    const float* Wq     = (const float*)d_in[3];
    const float* bq     = (const float*)d_in[4];
    const float* Wk     = (const float*)d_in[5];
    const float* bk     = (const float*)d_in[6];
    const float* Wv     = (const float*)d_in[7];
    const float* bv     = (const float*)d_in[8];
    float* out = (float*)d_out;

    cudaFuncSetAttribute(attn, cudaFuncAttributeMaxDynamicSharedMemorySize, SM_BYTES);

    dim3 g(HID / GN, ROWS / GM, 3);
    qkv_gemm<<<g, 256>>>(hidden, Wq, bq, Wk, bk, Wv, bv);
    attn<<<ROWS / TQ, 384, SM_BYTES>>>(mask, rel, out);
}

// round 7
// speedup vs baseline: 1.3423x; 1.2828x over previous
#include <cuda_runtime.h>

#define Bb  4
#define Ss  512
#define NHh 12
#define DHh 64
#define HID 768
#define ROWS (Bb*Ss)   // 2048

typedef unsigned long long ull;

// packed fp32x2 (Blackwell)
#define PK2(dst, lo, hi)  asm("mov.b64 %0, {%1,%2};" : "=l"(dst) : "f"(lo), "f"(hi))
#define UPK2(lo, hi, src) asm("mov.b64 {%0,%1}, %2;" : "=f"(lo), "=f"(hi) : "l"(src))
#define FMA2(acc, a, b)   asm("fma.rn.f32x2 %0, %1, %2, %0;" : "+l"(acc) : "l"(a), "l"(b))
#define ADD2(d, a, b)     asm("add.rn.f32x2 %0, %1, %2;" : "=l"(d) : "l"(a), "l"(b))
#define MUL2(d, a, b)     asm("mul.rn.f32x2 %0, %1, %2;" : "=l"(d) : "l"(a), "l"(b))

__device__ float g_q [ROWS*HID];          // [B,S,HID]
__device__ float g_kt[ROWS*HID];          // [B,NH,DH,S]
__device__ float g_v [ROWS*HID];          // [B,S,HID]

// ---------------- QKV GEMM: 128x128x8, 8x8/thread, prefetch (unchanged) ----
#define GM 128
#define GN 128
#define GK 8

__global__ void __launch_bounds__(256, 2) qkv_gemm(
    const float* __restrict__ A,
    const float* __restrict__ Wq, const float* __restrict__ bq,
    const float* __restrict__ Wk, const float* __restrict__ bk,
    const float* __restrict__ Wv, const float* __restrict__ bv)
{
    const int z = blockIdx.z;
    const float* W    = (z == 0) ? Wq : (z == 1) ? Wk : Wv;
    const float* bias = (z == 0) ? bq : (z == 1) ? bk : bv;

    __shared__ float As[GK][GM + 4];
    __shared__ float Ws[GK][GN];

    const int tid = threadIdx.x;
    const int rowBase = blockIdx.y * GM;
    const int colBase = blockIdx.x * GN;

    const int arow = tid >> 1;
    const int ak   = (tid & 1) * 4;
    const int wk   = tid >> 5;
    const int wn   = (tid & 31) * 4;

    const int tx = tid & 15;
    const int ty = tid >> 4;

    float4 aF = *(const float4*)&A[(rowBase + arow) * HID + ak];
    float4 wF = *(const float4*)&W[wk * HID + colBase + wn];

    float acc[8][8] = {};

    for (int k0 = 0; k0 < HID; k0 += GK) {
        As[ak + 0][arow] = aF.x;
        As[ak + 1][arow] = aF.y;
        As[ak + 2][arow] = aF.z;
        As[ak + 3][arow] = aF.w;
        *(float4*)&Ws[wk][wn] = wF;
        __syncthreads();

        if (k0 + GK < HID) {
            aF = *(const float4*)&A[(rowBase + arow) * HID + k0 + GK + ak];
            wF = *(const float4*)&W[(k0 + GK + wk) * HID + colBase + wn];
        }

        #pragma unroll
        for (int k = 0; k < GK; k++) {
            float4 a0 = *(const float4*)&As[k][ty * 8];
            float4 a1 = *(const float4*)&As[k][ty * 8 + 4];
            float4 b0 = *(const float4*)&Ws[k][tx * 8];
            float4 b1 = *(const float4*)&Ws[k][tx * 8 + 4];
            const float av[8] = {a0.x, a0.y, a0.z, a0.w, a1.x, a1.y, a1.z, a1.w};
            const float bv2[8] = {b0.x, b0.y, b0.z, b0.w, b1.x, b1.y, b1.z, b1.w};
            #pragma unroll
            for (int i = 0; i < 8; i++)
                #pragma unroll
                for (int j = 0; j < 8; j++)
                    acc[i][j] += av[i] * bv2[j];
        }
        __syncthreads();
    }

    #pragma unroll
    for (int i = 0; i < 8; i++) {
        const int row = rowBase + ty * 8 + i;
        #pragma unroll
        for (int j = 0; j < 8; j++) {
            const int col = colBase + tx * 8 + j;
            const float c = acc[i][j] + bias[col];
            if (z == 0) {
                g_q[row * HID + col] = c;
            } else if (z == 2) {
                g_v[row * HID + col] = c;
            } else {
                const int b = row >> 9, s = row & 511;
                const int h = col >> 6, d = col & 63;
                g_kt[((b * NHh + h) * DHh + d) * Ss + s] = c;
            }
        }
    }
}

// ---------------- fused relational attention, v7 (head-quads) -----------
// CTA = 4 q-rows, 384 threads = 12 warps = 3 quads(4 heads) x 4 subs.
//   score : sub = d-quarter, lane = k; partials -> SMEM exchange
//   softmax: warp = head (m/l in regs)
//   ctx   : sub = (d-half, k-half), lane = d; k-half partials combined at end
// rel SMEM layout [k][d][qi], row stride 260 floats (1040B == 16B mod 128):
// conflict-free for lane=k AND lane=d 16B reads, and for STS.128 staging.
#define TQ 4
#define TK 32
#define NBLK (Ss / TK)                 // 16
#define RROW 260
#define RELBUF (TK * RROW)             // 8320 floats

#define Q_OFF  (2 * RELBUF)            // 16640
#define SC_OFF (Q_OFF + HID * TQ)      // 19712
#define SP_OFF (SC_OFF + NHh * TK * TQ)       // 21248
#define AL_OFF (SP_OFF + 4 * NHh * TK * TQ)   // 27392
#define L_OFF  (AL_OFF + NHh * TQ)            // 27440
#define SM_FLOATS (L_OFF + NHh * TQ)          // 27488
#define SM_BYTES  (SM_FLOATS * 4)             // 109952

#define QSTRIDE (Ss * DHh)             // qi stride in rel gmem

__global__ void __launch_bounds__(384, 2) attn(
    const float* __restrict__ mask,   // [B,1,1,S]
    const float* __restrict__ rel,    // [B,S,S,DH]
    float* __restrict__ out)          // [B,S,HID]
{
    extern __shared__ float sm[];
    float* q_s  = sm + Q_OFF;          // [(h*64+d)*4 + qi], pre-scaled
    float* sc   = sm + SC_OFF;         // probs [(h*TK+k)*4 + qi]
    float* sp   = sm + SP_OFF;         // score partials [((su*12+h)*TK+k)*4+qi]
    float* al_s = sm + AL_OFF;         // alpha [h*4+qi]
    float* l_s  = sm + L_OFF;          // l     [h*4+qi]

    const int cta  = blockIdx.x;       // 512
    const int b    = cta >> 7;
    const int q0   = (cta & 127) << 2;
    const int tid  = threadIdx.x;
    const int wid  = tid >> 5;
    const int lane = tid & 31;

    const int z  = wid >> 2;           // quad 0..2
    const int su = wid & 3;            // sub  0..3
    const int h0 = z * 4;

    const float* relg = rel + (long)(b * Ss + q0) * Ss * DHh;

    // stage q
    for (int i = tid; i < HID; i += 384) {
        #pragma unroll
        for (int qi = 0; qi < TQ; qi++)
            q_s[i * TQ + qi] = g_q[(b * Ss + q0 + qi) * HID + i] * 0.125f;
    }

    // stage rel block 0 (thread = (k,d): 4 coalesced LDG + 1 STS.128)
    #pragma unroll
    for (int it = 0; it < 6; it++) {
        const int idx = tid + it * 384;
        if (idx < TK * DHh) {
            const int k = idx >> 6, d = idx & 63;
            const float* g = relg + (long)k * DHh + d;
            float4 w;
            w.x = g[0];
            w.y = g[QSTRIDE];
            w.z = g[2 * QSTRIDE];
            w.w = g[3 * QSTRIDE];
            *(float4*)&sm[k * RROW + d * 4] = w;
        }
    }
    __syncthreads();

    float m[TQ], l[TQ];
    #pragma unroll
    for (int qi = 0; qi < TQ; qi++) { m[qi] = -1e30f; l[qi] = 0.f; }

    ull c01[4] = {0, 0, 0, 0}, c23[4] = {0, 0, 0, 0};   // ctx [hh][qi-pairs]

    for (int blk = 0; blk < NBLK; blk++) {
        const int kb = blk * TK;
        float* relc = sm + (blk & 1) * RELBUF;

        // ---- SCORE: quad z, d-quarter su, lane = k
        {
            const int k = lane;
            ull a01[4] = {0, 0, 0, 0}, a23[4] = {0, 0, 0, 0};
            const float* ktb = g_kt + ((long)(b * NHh + h0) * DHh) * Ss + kb + k;
            const int d0 = su * 16;
            #pragma unroll
            for (int dd = 0; dd < 16; dd += 2) {
                float kv[8];
                #pragma unroll
                for (int hh = 0; hh < 4; hh++) {
                    kv[hh * 2 + 0] = ktb[(hh * DHh + d0 + dd) * Ss];
                    kv[hh * 2 + 1] = ktb[(hh * DHh + d0 + dd + 1) * Ss];
                }
                #pragma unroll
                for (int t = 0; t < 2; t++) {
                    const int d = d0 + dd + t;
                    float4 rr = *(const float4*)&relc[k * RROW + d * 4];
                    ull rr01, rr23;
                    PK2(rr01, rr.x, rr.y); PK2(rr23, rr.z, rr.w);
                    #pragma unroll
                    for (int hh = 0; hh < 4; hh++) {
                        float4 q4 = *(const float4*)&q_s[((h0 + hh) * DHh + d) * TQ];
                        ull kd, t01, t23, q01, q23;
                        PK2(kd, kv[hh * 2 + t], kv[hh * 2 + t]);
                        ADD2(t01, kd, rr01); ADD2(t23, kd, rr23);
                        PK2(q01, q4.x, q4.y); PK2(q23, q4.z, q4.w);
                        FMA2(a01[hh], q01, t01); FMA2(a23[hh], q23, t23);
                    }
                }
            }
            #pragma unroll
            for (int hh = 0; hh < 4; hh++) {
                float x0, x1, x2, x3;
                UPK2(x0, x1, a01[hh]); UPK2(x2, x3, a23[hh]);
                float4 w = {x0, x1, x2, x3};
                *(float4*)&sp[((su * NHh + h0 + hh) * TK + k) * TQ] = w;
            }
        }

        // ---- stage NEXT rel block into other buffer
        if (blk + 1 < NBLK) {
            float* reln = sm + ((blk + 1) & 1) * RELBUF;
            const long gb = (long)(kb + TK) * DHh;
            #pragma unroll
            for (int it = 0; it < 6; it++) {
                const int idx = tid + it * 384;
                if (idx < TK * DHh) {
                    const int k = idx >> 6, d = idx & 63;
                    const float* g = relg + gb + (long)k * DHh + d;
                    float4 w;
                    w.x = g[0];
                    w.y = g[QSTRIDE];
                    w.z = g[2 * QSTRIDE];
                    w.w = g[3 * QSTRIDE];
                    *(float4*)&reln[k * RROW + d * 4] = w;
                }
            }
        }
        __syncthreads();

        // ---- SOFTMAX: warp = head (wid), lane = k
        {
            const int h = wid, k = lane;
            float4 p0 = *(const float4*)&sp[((0 * NHh + h) * TK + k) * TQ];
            float4 p1 = *(const float4*)&sp[((1 * NHh + h) * TK + k) * TQ];
            float4 p2 = *(const float4*)&sp[((2 * NHh + h) * TK + k) * TQ];
            float4 p3 = *(const float4*)&sp[((3 * NHh + h) * TK + k) * TQ];
            const float mv = mask[b * Ss + kb + k];
            float s[TQ];
            s[0] = p0.x + p1.x + p2.x + p3.x + mv;
            s[1] = p0.y + p1.y + p2.y + p3.y + mv;
            s[2] = p0.z + p1.z + p2.z + p3.z + mv;
            s[3] = p0.w + p1.w + p2.w + p3.w + mv;
            float pr[TQ];
            #pragma unroll
            for (int qi = 0; qi < TQ; qi++) {
                float mx = s[qi];
                #pragma unroll
                for (int o = 16; o; o >>= 1)
                    mx = fmaxf(mx, __shfl_xor_sync(0xffffffffu, mx, o));
                const float mnew = fmaxf(m[qi], mx);
                const float p = __expf(s[qi] - mnew);
                float ls = p;
                #pragma unroll
                for (int o = 16; o; o >>= 1)
                    ls += __shfl_xor_sync(0xffffffffu, ls, o);
                const float alpha = __expf(m[qi] - mnew);
                l[qi] = l[qi] * alpha + ls;
                m[qi] = mnew;
                pr[qi] = p;
                if (lane == 0) al_s[h * TQ + qi] = alpha;
            }
            float4 w = {pr[0], pr[1], pr[2], pr[3]};
            *(float4*)&sc[(h * TK + k) * TQ] = w;
            if (blk == NBLK - 1 && lane == 0) {
                #pragma unroll
                for (int qi = 0; qi < TQ; qi++) l_s[h * TQ + qi] = l[qi];
            }
        }
        __syncthreads();

        // ---- CTX: quad z, sub = (d-half e, k-half j), lane = d in half
        {
            const int e = su >> 1, j = su & 1;
            const int d = e * 32 + lane;
            #pragma unroll
            for (int hh = 0; hh < 4; hh++) {
                float4 al = *(const float4*)&al_s[(h0 + hh) * TQ];
                ull al01, al23;
                PK2(al01, al.x, al.y); PK2(al23, al.z, al.w);
                MUL2(c01[hh], c01[hh], al01);
                MUL2(c23[hh], c23[hh], al23);
            }
            const float* vb = g_v + (long)(b * Ss + kb + j * 16) * HID + d;
            #pragma unroll
            for (int kk = 0; kk < 16; kk += 2) {
                float vv[8];
                #pragma unroll
                for (int hh = 0; hh < 4; hh++) {
                    vv[hh * 2 + 0] = vb[kk * HID + (h0 + hh) * DHh];
                    vv[hh * 2 + 1] = vb[(kk + 1) * HID + (h0 + hh) * DHh];
                }
                #pragma unroll
                for (int t = 0; t < 2; t++) {
                    const int k = j * 16 + kk + t;
                    float4 rr = *(const float4*)&relc[k * RROW + d * 4];
                    ull rr01, rr23;
                    PK2(rr01, rr.x, rr.y); PK2(rr23, rr.z, rr.w);
                    #pragma unroll
                    for (int hh = 0; hh < 4; hh++) {
                        float4 p4 = *(const float4*)&sc[((h0 + hh) * TK + k) * TQ];
                        ull vd, u01, u23, p01, p23;
                        PK2(vd, vv[hh * 2 + t], vv[hh * 2 + t]);
                        ADD2(u01, vd, rr01); ADD2(u23, vd, rr23);
                        PK2(p01, p4.x, p4.y); PK2(p23, p4.z, p4.w);
                        FMA2(c01[hh], p01, u01); FMA2(c23[hh], p23, u23);
                    }
                }
            }
        }
        __syncthreads();
    }

    // ---- combine k-half partials and write out
    {
        const int e = su >> 1, j = su & 1;
        const int d = e * 32 + lane;
        float* cmb = sp;
        if (j == 0) {
            #pragma unroll
            for (int hh = 0; hh < 4; hh++) {
                float x0, x1, x2, x3;
                UPK2(x0, x1, c01[hh]); UPK2(x2, x3, c23[hh]);
                float4 w = {x0, x1, x2, x3};
                *(float4*)&cmb[((h0 + hh) * DHh + d) * TQ] = w;
            }
        }
        __syncthreads();
        if (j == 1) {
            #pragma unroll
            for (int hh = 0; hh < 4; hh++) {
                float4 o = *(const float4*)&cmb[((h0 + hh) * DHh + d) * TQ];
                float x0, x1, x2, x3;
                UPK2(x0, x1, c01[hh]); UPK2(x2, x3, c23[hh]);
                const float* lv = &l_s[(h0 + hh) * TQ];
                const float r0 = (o.x + x0) / lv[0];
                const float r1 = (o.y + x1) / lv[1];
                const float r2 = (o.z + x2) / lv[2];
                const float r3 = (o.w + x3) / lv[3];
                const long base = (long)(b * Ss + q0) * HID + (h0 + hh) * DHh + d;
                out[base]           = r0;
                out[base + HID]     = r1;
                out[base + 2 * HID] = r2;
                out[base + 3 * HID] = r3;
            }
        }
    }
}

extern "C" void kernel_launch(void* const* d_in, const int* in_sizes, int n_in,
                              void* d_out, int out_size)
{
    const float* hidden = (const float*)d_in[0];
    const float* mask   = (const float*)d_in[1];
    const float* rel    = (const float*)d_in[2];
    const float* Wq     = (const float*)d_in[3];
    const float* bq     = (const float*)d_in[4];
    const float* Wk     = (const float*)d_in[5];
    const float* bk     = (const float*)d_in[6];
    const float* Wv     = (const float*)d_in[7];
    const float* bv     = (const float*)d_in[8];
    float* out = (float*)d_out;

    cudaFuncSetAttribute(attn, cudaFuncAttributeMaxDynamicSharedMemorySize, SM_BYTES);

    dim3 g(HID / GN, ROWS / GM, 3);
    qkv_gemm<<<g, 256>>>(hidden, Wq, bq, Wk, bk, Wv, bv);
    attn<<<ROWS / TQ, 384, SM_BYTES>>>(mask, rel, out);
}

// round 8
// speedup vs baseline: 1.4756x; 1.0993x over previous
#include <cuda_runtime.h>

#define Bb  4
#define Ss  512
#define NHh 12
#define DHh 64
#define HID 768
#define ROWS (Bb*Ss)   // 2048

typedef unsigned long long ull;
typedef unsigned int uint;

// packed fp32x2 (Blackwell)
#define PK2(dst, lo, hi)  asm("mov.b64 %0, {%1,%2};" : "=l"(dst) : "f"(lo), "f"(hi))
#define UPK2(lo, hi, src) asm("mov.b64 {%0,%1}, %2;" : "=f"(lo), "=f"(hi) : "l"(src))
#define FMA2(acc, a, b)   asm("fma.rn.f32x2 %0, %1, %2, %0;" : "+l"(acc) : "l"(a), "l"(b))
#define ADD2(d, a, b)     asm("add.rn.f32x2 %0, %1, %2;" : "=l"(d) : "l"(a), "l"(b))
#define MUL2(d, a, b)     asm("mul.rn.f32x2 %0, %1, %2;" : "=l"(d) : "l"(a), "l"(b))

// fp16 pack/unpack
#define F2TOH2(dst, lo, hi) \
    asm("cvt.rn.f16x2.f32 %0, %2, %1;" : "=r"(dst) : "f"(lo), "f"(hi))
#define H2TOF2(dst, h2) \
    asm("{.reg .b16 l,h; .reg .f32 f0,f1; mov.b32 {l,h}, %1;" \
        " cvt.f32.f16 f0, l; cvt.f32.f16 f1, h; mov.b64 %0, {f0,f1};}" \
        : "=l"(dst) : "r"(h2))
#define H2TO2F(flo, fhi, h2) \
    asm("{.reg .b16 l,h; mov.b32 {l,h}, %2;" \
        " cvt.f32.f16 %0, l; cvt.f32.f16 %1, h;}" \
        : "=f"(flo), "=f"(fhi) : "r"(h2))

// scratch (allocation-free rule: __device__ globals)
__device__ float g_q  [ROWS*HID];                 // [B,S,HID] fp32
__device__ uint  g_kth[Bb*NHh*(DHh/2)*Ss];        // K fp16 [b,h,dp,k] half2=(d,d+1)
__device__ uint  g_vh [Bb*(Ss/2)*HID];            // V fp16 [b,kp,col] half2=(k,k+1)

// ---------------- QKV GEMM: 128x128x8, 8x8/thread, prefetch -------------
#define GM 128
#define GN 128
#define GK 8

__global__ void __launch_bounds__(256, 2) qkv_gemm(
    const float* __restrict__ A,
    const float* __restrict__ Wq, const float* __restrict__ bq,
    const float* __restrict__ Wk, const float* __restrict__ bk,
    const float* __restrict__ Wv, const float* __restrict__ bv)
{
    const int z = blockIdx.z;
    const float* W    = (z == 0) ? Wq : (z == 1) ? Wk : Wv;
    const float* bias = (z == 0) ? bq : (z == 1) ? bk : bv;

    __shared__ float As[GK][GM + 4];
    __shared__ float Ws[GK][GN];

    const int tid = threadIdx.x;
    const int rowBase = blockIdx.y * GM;
    const int colBase = blockIdx.x * GN;

    const int arow = tid >> 1;
    const int ak   = (tid & 1) * 4;
    const int wk   = tid >> 5;
    const int wn   = (tid & 31) * 4;

    const int tx = tid & 15;
    const int ty = tid >> 4;

    float4 aF = *(const float4*)&A[(rowBase + arow) * HID + ak];
    float4 wF = *(const float4*)&W[wk * HID + colBase + wn];

    float acc[8][8] = {};

    for (int k0 = 0; k0 < HID; k0 += GK) {
        As[ak + 0][arow] = aF.x;
        As[ak + 1][arow] = aF.y;
        As[ak + 2][arow] = aF.z;
        As[ak + 3][arow] = aF.w;
        *(float4*)&Ws[wk][wn] = wF;
        __syncthreads();

        if (k0 + GK < HID) {
            aF = *(const float4*)&A[(rowBase + arow) * HID + k0 + GK + ak];
            wF = *(const float4*)&W[(k0 + GK + wk) * HID + colBase + wn];
        }

        #pragma unroll
        for (int k = 0; k < GK; k++) {
            float4 a0 = *(const float4*)&As[k][ty * 8];
            float4 a1 = *(const float4*)&As[k][ty * 8 + 4];
            float4 b0 = *(const float4*)&Ws[k][tx * 8];
            float4 b1 = *(const float4*)&Ws[k][tx * 8 + 4];
            const float av[8] = {a0.x, a0.y, a0.z, a0.w, a1.x, a1.y, a1.z, a1.w};
            const float bv2[8] = {b0.x, b0.y, b0.z, b0.w, b1.x, b1.y, b1.z, b1.w};
            #pragma unroll
            for (int i = 0; i < 8; i++)
                #pragma unroll
                for (int j = 0; j < 8; j++)
                    acc[i][j] += av[i] * bv2[j];
        }
        __syncthreads();
    }

    // bias
    #pragma unroll
    for (int i = 0; i < 8; i++)
        #pragma unroll
        for (int j = 0; j < 8; j++)
            acc[i][j] += bias[colBase + tx * 8 + j];

    if (z == 0) {
        #pragma unroll
        for (int i = 0; i < 8; i++) {
            const int row = rowBase + ty * 8 + i;
            #pragma unroll
            for (int j = 0; j < 8; j++)
                g_q[row * HID + colBase + tx * 8 + j] = acc[i][j];
        }
    } else if (z == 1) {
        // K: [b,h,dp,k] half2 over d-pairs
        #pragma unroll
        for (int i = 0; i < 8; i++) {
            const int row = rowBase + ty * 8 + i;     // (b, s=k-pos)
            const int b = row >> 9, s = row & 511;
            #pragma unroll
            for (int jp = 0; jp < 4; jp++) {
                const int col = colBase + tx * 8 + jp * 2;
                const int h = col >> 6, dp = (col & 63) >> 1;
                uint u;
                F2TOH2(u, acc[i][jp * 2], acc[i][jp * 2 + 1]);
                g_kth[((b * NHh + h) * (DHh / 2) + dp) * Ss + s] = u;
            }
        }
    } else {
        // V: [b,kp,col] half2 over k-pairs (rows i, i+1)
        #pragma unroll
        for (int ip = 0; ip < 4; ip++) {
            const int row = rowBase + ty * 8 + ip * 2;
            const int b = row >> 9, kp = (row & 511) >> 1;
            #pragma unroll
            for (int j = 0; j < 8; j++) {
                const int col = colBase + tx * 8 + j;
                uint u;
                F2TOH2(u, acc[ip * 2][j], acc[ip * 2 + 1][j]);
                g_vh[(b * (Ss / 2) + kp) * HID + col] = u;
            }
        }
    }
}

// ---------------- fused relational attention, v8 (fp16 K/V/rel) ---------
// CTA = 4 q-rows, 384 threads = 12 warps = 3 quads(4 heads) x 4 subs.
// rel in SMEM as fp16 (4 qi = 8B), row stride 65 uint2 (520B == 8B mod 128):
// conflict-free for lane=k and lane=d. K d-pair / V k-pair fp16 halve LDG wf.
#define TQ 4
#define TK 32
#define NBLK (Ss / TK)                 // 16
#define RROW 65                        // uint2 slots per k-row (64 d + pad)
#define RELB_U2 (TK * RROW)            // 2080 uint2 per buffer

#define REL_BYTES (RELB_U2 * 8)        // 16640
#define Q_B   (2 * REL_BYTES)          // 33280
#define SC_B  (Q_B + HID * TQ * 4)     // 45568
#define SP_B  (SC_B + NHh * TK * TQ * 4)        // 51712
#define AL_B  (SP_B + 4 * NHh * TK * 8)         // 64000
#define L_B   (AL_B + NHh * TQ * 4)             // 64192
#define SM_BYTES (L_B + NHh * TQ * 4)           // 64384

#define QSTRIDE (Ss * DHh)             // qi stride in rel gmem

__global__ void __launch_bounds__(384, 2) attn(
    const float* __restrict__ mask,   // [B,1,1,S]
    const float* __restrict__ rel,    // [B,S,S,DH]
    float* __restrict__ out)          // [B,S,HID]
{
    extern __shared__ char smc[];
    uint2* relbuf = (uint2*)smc;              // [buf][k*RROW + d]
    float* q_s    = (float*)(smc + Q_B);      // [(h*64+d)*4 + qi]
    float* sc     = (float*)(smc + SC_B);     // probs fp32 [(h*TK+k)*4+qi]
    uint2* sp8    = (uint2*)(smc + SP_B);     // partials fp16 [(su*12+h)*TK+k]
    float* al_s   = (float*)(smc + AL_B);     // alpha [h*4+qi]
    float* l_s    = (float*)(smc + L_B);      // l     [h*4+qi]

    const int cta  = blockIdx.x;       // 512
    const int b    = cta >> 7;
    const int q0   = (cta & 127) << 2;
    const int tid  = threadIdx.x;
    const int wid  = tid >> 5;
    const int lane = tid & 31;

    const int z  = wid >> 2;           // quad 0..2
    const int su = wid & 3;            // sub  0..3
    const int h0 = z * 4;

    const float* relg = rel + (long)(b * Ss + q0) * Ss * DHh;

    // stage q (fp32)
    for (int i = tid; i < HID; i += 384) {
        #pragma unroll
        for (int qi = 0; qi < TQ; qi++)
            q_s[i * TQ + qi] = g_q[(b * Ss + q0 + qi) * HID + i] * 0.125f;
    }

    // stage rel block 0: thread=(k,d), 4 LDG + pack fp16 + STS.64
    #pragma unroll
    for (int it = 0; it < 6; it++) {
        const int idx = tid + it * 384;
        if (idx < TK * DHh) {
            const int k = idx >> 6, d = idx & 63;
            const float* g = relg + (long)k * DHh + d;
            const float v0 = g[0];
            const float v1 = g[QSTRIDE];
            const float v2 = g[2 * QSTRIDE];
            const float v3 = g[3 * QSTRIDE];
            uint2 w;
            F2TOH2(w.x, v0, v1);
            F2TOH2(w.y, v2, v3);
            relbuf[k * RROW + d] = w;
        }
    }
    __syncthreads();

    float m[TQ], l[TQ];
    #pragma unroll
    for (int qi = 0; qi < TQ; qi++) { m[qi] = -1e30f; l[qi] = 0.f; }

    ull c01[4] = {0, 0, 0, 0}, c23[4] = {0, 0, 0, 0};   // ctx [hh][qi-pairs]

    for (int blk = 0; blk < NBLK; blk++) {
        const int kb = blk * TK;
        const uint2* relc = relbuf + (blk & 1) * RELB_U2;

        // ---- SCORE: quad z, d-quarter su, lane = k
        {
            const int k = lane;
            ull a01[4] = {0, 0, 0, 0}, a23[4] = {0, 0, 0, 0};
            const uint* ktb = g_kth + ((long)(b * NHh + h0) * (DHh / 2)) * Ss + kb + k;
            const int dp0 = su * 8;
            uint kraw[4];
            #pragma unroll
            for (int hh = 0; hh < 4; hh++)
                kraw[hh] = ktb[(hh * (DHh / 2) + dp0) * Ss];
            #pragma unroll
            for (int dpi = 0; dpi < 8; dpi++) {
                uint nk[4];
                if (dpi < 7) {
                    #pragma unroll
                    for (int hh = 0; hh < 4; hh++)
                        nk[hh] = ktb[(hh * (DHh / 2) + dp0 + dpi + 1) * Ss];
                }
                float kv[8];
                #pragma unroll
                for (int hh = 0; hh < 4; hh++)
                    H2TO2F(kv[hh * 2], kv[hh * 2 + 1], kraw[hh]);
                #pragma unroll
                for (int t = 0; t < 2; t++) {
                    const int d = su * 16 + dpi * 2 + t;
                    uint2 r8 = relc[k * RROW + d];
                    ull rr01, rr23;
                    H2TOF2(rr01, r8.x);
                    H2TOF2(rr23, r8.y);
                    #pragma unroll
                    for (int hh = 0; hh < 4; hh++) {
                        float4 q4 = *(const float4*)&q_s[((h0 + hh) * DHh + d) * TQ];
                        ull kd, t01, t23, q01, q23;
                        PK2(kd, kv[hh * 2 + t], kv[hh * 2 + t]);
                        ADD2(t01, kd, rr01); ADD2(t23, kd, rr23);
                        PK2(q01, q4.x, q4.y); PK2(q23, q4.z, q4.w);
                        FMA2(a01[hh], q01, t01); FMA2(a23[hh], q23, t23);
                    }
                }
                if (dpi < 7) {
                    #pragma unroll
                    for (int hh = 0; hh < 4; hh++) kraw[hh] = nk[hh];
                }
            }
            #pragma unroll
            for (int hh = 0; hh < 4; hh++) {
                float x0, x1, x2, x3;
                UPK2(x0, x1, a01[hh]); UPK2(x2, x3, a23[hh]);
                uint2 w;
                F2TOH2(w.x, x0, x1);
                F2TOH2(w.y, x2, x3);
                sp8[((su * NHh + h0 + hh) * TK + k)] = w;
            }
        }

        // ---- stage NEXT rel block into other buffer
        if (blk + 1 < NBLK) {
            uint2* reln = relbuf + ((blk + 1) & 1) * RELB_U2;
            const long gb = (long)(kb + TK) * DHh;
            #pragma unroll
            for (int it = 0; it < 6; it++) {
                const int idx = tid + it * 384;
                if (idx < TK * DHh) {
                    const int k = idx >> 6, d = idx & 63;
                    const float* g = relg + gb + (long)k * DHh + d;
                    const float v0 = g[0];
                    const float v1 = g[QSTRIDE];
                    const float v2 = g[2 * QSTRIDE];
                    const float v3 = g[3 * QSTRIDE];
                    uint2 w;
                    F2TOH2(w.x, v0, v1);
                    F2TOH2(w.y, v2, v3);
                    reln[k * RROW + d] = w;
                }
            }
        }
        __syncthreads();

        // ---- SOFTMAX: warp = head (wid), lane = k
        {
            const int h = wid, k = lane;
            float s[TQ] = {0.f, 0.f, 0.f, 0.f};
            #pragma unroll
            for (int u = 0; u < 4; u++) {
                uint2 P = sp8[((u * NHh + h) * TK + k)];
                float e0, e1, e2, e3;
                H2TO2F(e0, e1, P.x);
                H2TO2F(e2, e3, P.y);
                s[0] += e0; s[1] += e1; s[2] += e2; s[3] += e3;
            }
            const float mv = mask[b * Ss + kb + k];
            float pr[TQ];
            #pragma unroll
            for (int qi = 0; qi < TQ; qi++) {
                s[qi] += mv;
                float mx = s[qi];
                #pragma unroll
                for (int o = 16; o; o >>= 1)
                    mx = fmaxf(mx, __shfl_xor_sync(0xffffffffu, mx, o));
                const float mnew = fmaxf(m[qi], mx);
                const float p = __expf(s[qi] - mnew);
                float ls = p;
                #pragma unroll
                for (int o = 16; o; o >>= 1)
                    ls += __shfl_xor_sync(0xffffffffu, ls, o);
                const float alpha = __expf(m[qi] - mnew);
                l[qi] = l[qi] * alpha + ls;
                m[qi] = mnew;
                pr[qi] = p;
                if (lane == 0) al_s[h * TQ + qi] = alpha;
            }
            float4 w = {pr[0], pr[1], pr[2], pr[3]};
            *(float4*)&sc[(h * TK + k) * TQ] = w;
            if (blk == NBLK - 1 && lane == 0) {
                #pragma unroll
                for (int qi = 0; qi < TQ; qi++) l_s[h * TQ + qi] = l[qi];
            }
        }
        __syncthreads();

        // ---- CTX: quad z, sub = (d-half e, k-half j), lane = d in half
        {
            const int e = su >> 1, j = su & 1;
            const int d = e * 32 + lane;
            #pragma unroll
            for (int hh = 0; hh < 4; hh++) {
                float4 al = *(const float4*)&al_s[(h0 + hh) * TQ];
                ull al01, al23;
                PK2(al01, al.x, al.y); PK2(al23, al.z, al.w);
                MUL2(c01[hh], c01[hh], al01);
                MUL2(c23[hh], c23[hh], al23);
            }
            const uint* vb = g_vh + (long)(b * (Ss / 2) + ((kb >> 1) + j * 8)) * HID + d;
            #pragma unroll
            for (int kkp = 0; kkp < 8; kkp++) {
                uint vraw[4];
                #pragma unroll
                for (int hh = 0; hh < 4; hh++)
                    vraw[hh] = vb[kkp * HID + (h0 + hh) * DHh];
                float vv[8];
                #pragma unroll
                for (int hh = 0; hh < 4; hh++)
                    H2TO2F(vv[hh * 2], vv[hh * 2 + 1], vraw[hh]);
                #pragma unroll
                for (int t = 0; t < 2; t++) {
                    const int k = j * 16 + kkp * 2 + t;
                    uint2 r8 = relc[k * RROW + d];
                    ull rr01, rr23;
                    H2TOF2(rr01, r8.x);
                    H2TOF2(rr23, r8.y);
                    #pragma unroll
                    for (int hh = 0; hh < 4; hh++) {
                        float4 p4 = *(const float4*)&sc[((h0 + hh) * TK + k) * TQ];
                        ull vd, u01, u23, p01, p23;
                        PK2(vd, vv[hh * 2 + t], vv[hh * 2 + t]);
                        ADD2(u01, vd, rr01); ADD2(u23, vd, rr23);
                        PK2(p01, p4.x, p4.y); PK2(p23, p4.z, p4.w);
                        FMA2(c01[hh], p01, u01); FMA2(c23[hh], p23, u23);
                    }
                }
            }
        }
        __syncthreads();
    }

    // ---- combine k-half partials and write out
    {
        const int e = su >> 1, j = su & 1;
        const int d = e * 32 + lane;
        float* cmb = (float*)sp8;          // reuse sp region (12 KB needed)
        if (j == 0) {
            #pragma unroll
            for (int hh = 0; hh < 4; hh++) {
                float x0, x1, x2, x3;
                UPK2(x0, x1, c01[hh]); UPK2(x2, x3, c23[hh]);
                float4 w = {x0, x1, x2, x3};
                *(float4*)&cmb[((h0 + hh) * DHh + d) * TQ] = w;
            }
        }
        __syncthreads();
        if (j == 1) {
            #pragma unroll
            for (int hh = 0; hh < 4; hh++) {
                float4 o = *(const float4*)&cmb[((h0 + hh) * DHh + d) * TQ];
                float x0, x1, x2, x3;
                UPK2(x0, x1, c01[hh]); UPK2(x2, x3, c23[hh]);
                const float* lv = &l_s[(h0 + hh) * TQ];
                const float r0 = (o.x + x0) / lv[0];
                const float r1 = (o.y + x1) / lv[1];
                const float r2 = (o.z + x2) / lv[2];
                const float r3 = (o.w + x3) / lv[3];
                const long base = (long)(b * Ss + q0) * HID + (h0 + hh) * DHh + d;
                out[base]           = r0;
                out[base + HID]     = r1;
                out[base + 2 * HID] = r2;
                out[base + 3 * HID] = r3;
            }
        }
    }
}

extern "C" void kernel_launch(void* const* d_in, const int* in_sizes, int n_in,
                              void* d_out, int out_size)
{
    const float* hidden = (const float*)d_in[0];
    const float* mask   = (const float*)d_in[1];
    const float* rel    = (const float*)d_in[2];
    const float* Wq     = (const float*)d_in[3];
    const float* bq     = (const float*)d_in[4];
    const float* Wk     = (const float*)d_in[5];
    const float* bk     = (const float*)d_in[6];
    const float* Wv     = (const float*)d_in[7];
    const float* bv     = (const float*)d_in[8];
    float* out = (float*)d_out;

    cudaFuncSetAttribute(attn, cudaFuncAttributeMaxDynamicSharedMemorySize, SM_BYTES);

    dim3 g(HID / GN, ROWS / GM, 3);
    qkv_gemm<<<g, 256>>>(hidden, Wq, bq, Wk, bk, Wv, bv);
    attn<<<ROWS / TQ, 384, SM_BYTES>>>(mask, rel, out);
}

// round 9
// speedup vs baseline: 1.9400x; 1.3147x over previous
#include <cuda_runtime.h>
#include <cuda_fp16.h>

#define Bb  4
#define Ss  512
#define NHh 12
#define DHh 64
#define HID 768
#define ROWS (Bb*Ss)   // 2048

typedef unsigned long long ull;
typedef unsigned int uint;

// packed fp32x2 (Blackwell)
#define PK2(dst, lo, hi)  asm("mov.b64 %0, {%1,%2};" : "=l"(dst) : "f"(lo), "f"(hi))
#define UPK2(lo, hi, src) asm("mov.b64 {%0,%1}, %2;" : "=f"(lo), "=f"(hi) : "l"(src))
#define FMA2(acc, a, b)   asm("fma.rn.f32x2 %0, %1, %2, %0;" : "+l"(acc) : "l"(a), "l"(b))
#define ADD2(d, a, b)     asm("add.rn.f32x2 %0, %1, %2;" : "=l"(d) : "l"(a), "l"(b))
#define MUL2(d, a, b)     asm("mul.rn.f32x2 %0, %1, %2;" : "=l"(d) : "l"(a), "l"(b))

// fp16 pack/unpack  (F2TOH2(dst, lo, hi): lo -> low half)
#define F2TOH2(dst, lo, hi) \
    asm("cvt.rn.f16x2.f32 %0, %2, %1;" : "=r"(dst) : "f"(lo), "f"(hi))
#define H2TOF2(dst, h2) \
    asm("{.reg .b16 l,h; .reg .f32 f0,f1; mov.b32 {l,h}, %1;" \
        " cvt.f32.f16 f0, l; cvt.f32.f16 f1, h; mov.b64 %0, {f0,f1};}" \
        : "=l"(dst) : "r"(h2))
#define H2TO2F(flo, fhi, h2) \
    asm("{.reg .b16 l,h; mov.b32 {l,h}, %2;" \
        " cvt.f32.f16 %0, l; cvt.f32.f16 %1, h;}" \
        : "=f"(flo), "=f"(fhi) : "r"(h2))

// tensor-core primitives
#define LDSM4(d0,d1,d2,d3,a) \
    asm volatile("ldmatrix.sync.aligned.m8n8.x4.shared.b16 {%0,%1,%2,%3}, [%4];" \
        : "=r"(d0),"=r"(d1),"=r"(d2),"=r"(d3) : "r"(a))
#define LDSM4T(d0,d1,d2,d3,a) \
    asm volatile("ldmatrix.sync.aligned.m8n8.x4.trans.shared.b16 {%0,%1,%2,%3}, [%4];" \
        : "=r"(d0),"=r"(d1),"=r"(d2),"=r"(d3) : "r"(a))
#define MMA16816(c0,c1,c2,c3,a0,a1,a2,a3,b0,b1) \
    asm volatile("mma.sync.aligned.m16n8k16.row.col.f32.f16.f16.f32 " \
        "{%0,%1,%2,%3},{%4,%5,%6,%7},{%8,%9},{%0,%1,%2,%3};" \
        : "+f"(c0),"+f"(c1),"+f"(c2),"+f"(c3) \
        : "r"(a0),"r"(a1),"r"(a2),"r"(a3),"r"(b0),"r"(b1))

__device__ __forceinline__ uint smem_u32(const void* p) {
    uint r;
    asm("{.reg .u64 t; cvta.to.shared.u64 t, %1; cvt.u32.u64 %0, t;}"
        : "=r"(r) : "l"(p));
    return r;
}

// scratch (allocation-free rule: __device__ globals)
__device__ float g_q  [ROWS*HID];                 // [B,S,HID] fp32
__device__ uint  g_kth[Bb*NHh*(DHh/2)*Ss];        // K fp16 [b,h,dp,k] half2=(d,d+1)
__device__ uint  g_vh [Bb*(Ss/2)*HID];            // V fp16 half2=(k,k+8) pairs

// ---------------- QKV GEMM: HMMA split-fp16 (error ~fp32) ----------------
// 128x128 tile, K-step 16, 8 warps x (64x32). D = Ah*Wh + Ah*Wl + Al*Wh.
#define SA_STR 24     // halfs per A smem row (16 used + pad, conflict-free)
#define SW_STR 136    // halfs per W smem row (128 used + pad, conflict-free)

__global__ void __launch_bounds__(256) qkv_gemm(
    const float* __restrict__ A,
    const float* __restrict__ Wq, const float* __restrict__ bq,
    const float* __restrict__ Wk, const float* __restrict__ bk,
    const float* __restrict__ Wv, const float* __restrict__ bv)
{
    const int z = blockIdx.z;
    const float* W    = (z == 0) ? Wq : (z == 1) ? Wk : Wv;
    const float* bias = (z == 0) ? bq : (z == 1) ? bk : bv;

    __shared__ __align__(16) half sAhi[128 * SA_STR];
    __shared__ __align__(16) half sAlo[128 * SA_STR];
    __shared__ __align__(16) half sWhi[16 * SW_STR];
    __shared__ __align__(16) half sWlo[16 * SW_STR];

    const int tid  = threadIdx.x;
    const int wid  = tid >> 5;
    const int lane = tid & 31;
    const int wm   = wid >> 2;       // 0..1 (m 64-half)
    const int wn   = wid & 3;        // 0..3 (n 32-slice)
    const int rowBase = blockIdx.y * 128;
    const int colBase = blockIdx.x * 128;

    // staging indices
    const int ar = tid >> 2;              // A rows ar, ar+64
    const int ac = (tid & 3) * 4;         // A col group
    const int wr = tid >> 5;              // W rows wr, wr+8
    const int wc = (tid & 31) * 4;        // W col group

    const uint sAhiB = smem_u32(sAhi), sAloB = smem_u32(sAlo);
    const uint sWhiB = smem_u32(sWhi), sWloB = smem_u32(sWlo);

    float4 a0f = *(const float4*)&A[(rowBase + ar) * HID + ac];
    float4 a1f = *(const float4*)&A[(rowBase + ar + 64) * HID + ac];
    float4 w0f = *(const float4*)&W[wr * HID + colBase + wc];
    float4 w1f = *(const float4*)&W[(wr + 8) * HID + colBase + wc];

    float acc[4][4][4] = {};

    // ldmatrix lane address components
    const int l15 = lane & 15;
    const int l16 = (lane >> 4) * 8;

    for (int k0 = 0; k0 < HID; k0 += 16) {
        // ---- stage with hi/lo split
        {
            uint h0, h1, l0, l1; float rx, ry, rz, rw;
            #define CVSPLIT(v) \
                F2TOH2(h0, v.x, v.y); F2TOH2(h1, v.z, v.w); \
                H2TO2F(rx, ry, h0);   H2TO2F(rz, rw, h1); \
                F2TOH2(l0, v.x - rx, v.y - ry); F2TOH2(l1, v.z - rz, v.w - rw);
            CVSPLIT(a0f);
            *(uint2*)&sAhi[ar * SA_STR + ac] = make_uint2(h0, h1);
            *(uint2*)&sAlo[ar * SA_STR + ac] = make_uint2(l0, l1);
            CVSPLIT(a1f);
            *(uint2*)&sAhi[(ar + 64) * SA_STR + ac] = make_uint2(h0, h1);
            *(uint2*)&sAlo[(ar + 64) * SA_STR + ac] = make_uint2(l0, l1);
            CVSPLIT(w0f);
            *(uint2*)&sWhi[wr * SW_STR + wc] = make_uint2(h0, h1);
            *(uint2*)&sWlo[wr * SW_STR + wc] = make_uint2(l0, l1);
            CVSPLIT(w1f);
            *(uint2*)&sWhi[(wr + 8) * SW_STR + wc] = make_uint2(h0, h1);
            *(uint2*)&sWlo[(wr + 8) * SW_STR + wc] = make_uint2(l0, l1);
            #undef CVSPLIT
        }
        __syncthreads();

        if (k0 + 16 < HID) {
            a0f = *(const float4*)&A[(rowBase + ar) * HID + k0 + 16 + ac];
            a1f = *(const float4*)&A[(rowBase + ar + 64) * HID + k0 + 16 + ac];
            w0f = *(const float4*)&W[(k0 + 16 + wr) * HID + colBase + wc];
            w1f = *(const float4*)&W[(k0 + 16 + wr + 8) * HID + colBase + wc];
        }

        // ---- B fragments (2 n16-groups x hi/lo)
        uint bh[2][4], bl[2][4];
        #pragma unroll
        for (int nt = 0; nt < 2; nt++) {
            const uint off = (uint)(l15 * SW_STR + wn * 32 + nt * 16 + l16) * 2;
            LDSM4T(bh[nt][0], bh[nt][1], bh[nt][2], bh[nt][3], sWhiB + off);
            LDSM4T(bl[nt][0], bl[nt][1], bl[nt][2], bl[nt][3], sWloB + off);
        }

        // ---- A fragments per m-tile, 3 MMA combos
        #pragma unroll
        for (int mt = 0; mt < 4; mt++) {
            const uint aoff = (uint)((wm * 64 + mt * 16 + l15) * SA_STR + l16) * 2;
            uint ah[4], al[4];
            LDSM4(ah[0], ah[1], ah[2], ah[3], sAhiB + aoff);
            LDSM4(al[0], al[1], al[2], al[3], sAloB + aoff);
            #pragma unroll
            for (int n8 = 0; n8 < 4; n8++) {
                const int nt = n8 >> 1, hb = (n8 & 1) * 2;
                float* c = acc[mt][n8];
                MMA16816(c[0], c[1], c[2], c[3],
                         ah[0], ah[1], ah[2], ah[3], bh[nt][hb], bh[nt][hb + 1]);
                MMA16816(c[0], c[1], c[2], c[3],
                         ah[0], ah[1], ah[2], ah[3], bl[nt][hb], bl[nt][hb + 1]);
                MMA16816(c[0], c[1], c[2], c[3],
                         al[0], al[1], al[2], al[3], bh[nt][hb], bh[nt][hb + 1]);
            }
        }
        __syncthreads();
    }

    // ---- epilogue
    const int g = lane >> 2, tig = lane & 3;
    #pragma unroll
    for (int mt = 0; mt < 4; mt++) {
        const int row = rowBase + wm * 64 + mt * 16 + g;   // and row+8
        #pragma unroll
        for (int n8 = 0; n8 < 4; n8++) {
            const int col = colBase + wn * 32 + n8 * 8 + tig * 2;
            const float2 bb = *(const float2*)&bias[col];
            const float v00 = acc[mt][n8][0] + bb.x;
            const float v01 = acc[mt][n8][1] + bb.y;
            const float v10 = acc[mt][n8][2] + bb.x;
            const float v11 = acc[mt][n8][3] + bb.y;
            if (z == 0) {
                float2 s0 = {v00, v01}, s1 = {v10, v11};
                *(float2*)&g_q[row * HID + col] = s0;
                *(float2*)&g_q[(row + 8) * HID + col] = s1;
            } else if (z == 1) {
                const int b = row >> 9, s = row & 511;
                const int h = col >> 6, dp = (col & 63) >> 1;
                uint u0, u1;
                F2TOH2(u0, v00, v01);
                F2TOH2(u1, v10, v11);
                g_kth[((b * NHh + h) * (DHh / 2) + dp) * Ss + s]     = u0;
                g_kth[((b * NHh + h) * (DHh / 2) + dp) * Ss + s + 8] = u1;
            } else {
                const int b = row >> 9, s = row & 511;
                const int kp = ((s >> 4) << 3) | (s & 7);   // (k=s, k=s+8) pair
                uint u0, u1;
                F2TOH2(u0, v00, v10);
                F2TOH2(u1, v01, v11);
                g_vh[(b * (Ss / 2) + kp) * HID + col]     = u0;
                g_vh[(b * (Ss / 2) + kp) * HID + col + 1] = u1;
            }
        }
    }
}

// ---------------- fused relational attention, v8 (fp16 K/V/rel) ---------
// unchanged except ctx k-mapping: V half2 pairs are now (k, k+8).
#define TQ 4
#define TK 32
#define NBLK (Ss / TK)                 // 16
#define RROW 65                        // uint2 slots per k-row (64 d + pad)
#define RELB_U2 (TK * RROW)            // 2080 uint2 per buffer

#define REL_BYTES (RELB_U2 * 8)        // 16640
#define Q_B   (2 * REL_BYTES)          // 33280
#define SC_B  (Q_B + HID * TQ * 4)     // 45568
#define SP_B  (SC_B + NHh * TK * TQ * 4)        // 51712
#define AL_B  (SP_B + 4 * NHh * TK * 8)         // 64000
#define L_B   (AL_B + NHh * TQ * 4)             // 64192
#define SM_BYTES (L_B + NHh * TQ * 4)           // 64384

#define QSTRIDE (Ss * DHh)             // qi stride in rel gmem

__global__ void __launch_bounds__(384, 2) attn(
    const float* __restrict__ mask,   // [B,1,1,S]
    const float* __restrict__ rel,    // [B,S,S,DH]
    float* __restrict__ out)          // [B,S,HID]
{
    extern __shared__ char smc[];
    uint2* relbuf = (uint2*)smc;              // [buf][k*RROW + d]
    float* q_s    = (float*)(smc + Q_B);      // [(h*64+d)*4 + qi]
    float* sc     = (float*)(smc + SC_B);     // probs fp32 [(h*TK+k)*4+qi]
    uint2* sp8    = (uint2*)(smc + SP_B);     // partials fp16 [(su*12+h)*TK+k]
    float* al_s   = (float*)(smc + AL_B);     // alpha [h*4+qi]
    float* l_s    = (float*)(smc + L_B);      // l     [h*4+qi]

    const int cta  = blockIdx.x;       // 512
    const int b    = cta >> 7;
    const int q0   = (cta & 127) << 2;
    const int tid  = threadIdx.x;
    const int wid  = tid >> 5;
    const int lane = tid & 31;

    const int z  = wid >> 2;           // quad 0..2
    const int su = wid & 3;            // sub  0..3
    const int h0 = z * 4;

    const float* relg = rel + (long)(b * Ss + q0) * Ss * DHh;

    // stage q (fp32)
    for (int i = tid; i < HID; i += 384) {
        #pragma unroll
        for (int qi = 0; qi < TQ; qi++)
            q_s[i * TQ + qi] = g_q[(b * Ss + q0 + qi) * HID + i] * 0.125f;
    }

    // stage rel block 0: thread=(k,d), 4 LDG + pack fp16 + STS.64
    #pragma unroll
    for (int it = 0; it < 6; it++) {
        const int idx = tid + it * 384;
        if (idx < TK * DHh) {
            const int k = idx >> 6, d = idx & 63;
            const float* g = relg + (long)k * DHh + d;
            const float v0 = g[0];
            const float v1 = g[QSTRIDE];
            const float v2 = g[2 * QSTRIDE];
            const float v3 = g[3 * QSTRIDE];
            uint2 w;
            F2TOH2(w.x, v0, v1);
            F2TOH2(w.y, v2, v3);
            relbuf[k * RROW + d] = w;
        }
    }
    __syncthreads();

    float m[TQ], l[TQ];
    #pragma unroll
    for (int qi = 0; qi < TQ; qi++) { m[qi] = -1e30f; l[qi] = 0.f; }

    ull c01[4] = {0, 0, 0, 0}, c23[4] = {0, 0, 0, 0};   // ctx [hh][qi-pairs]

    for (int blk = 0; blk < NBLK; blk++) {
        const int kb = blk * TK;
        const uint2* relc = relbuf + (blk & 1) * RELB_U2;

        // ---- SCORE: quad z, d-quarter su, lane = k
        {
            const int k = lane;
            ull a01[4] = {0, 0, 0, 0}, a23[4] = {0, 0, 0, 0};
            const uint* ktb = g_kth + ((long)(b * NHh + h0) * (DHh / 2)) * Ss + kb + k;
            const int dp0 = su * 8;
            uint kraw[4];
            #pragma unroll
            for (int hh = 0; hh < 4; hh++)
                kraw[hh] = ktb[(hh * (DHh / 2) + dp0) * Ss];
            #pragma unroll
            for (int dpi = 0; dpi < 8; dpi++) {
                uint nk[4];
                if (dpi < 7) {
                    #pragma unroll
                    for (int hh = 0; hh < 4; hh++)
                        nk[hh] = ktb[(hh * (DHh / 2) + dp0 + dpi + 1) * Ss];
                }
                float kv[8];
                #pragma unroll
                for (int hh = 0; hh < 4; hh++)
                    H2TO2F(kv[hh * 2], kv[hh * 2 + 1], kraw[hh]);
                #pragma unroll
                for (int t = 0; t < 2; t++) {
                    const int d = su * 16 + dpi * 2 + t;
                    uint2 r8 = relc[k * RROW + d];
                    ull rr01, rr23;
                    H2TOF2(rr01, r8.x);
                    H2TOF2(rr23, r8.y);
                    #pragma unroll
                    for (int hh = 0; hh < 4; hh++) {
                        float4 q4 = *(const float4*)&q_s[((h0 + hh) * DHh + d) * TQ];
                        ull kd, t01, t23, q01, q23;
                        PK2(kd, kv[hh * 2 + t], kv[hh * 2 + t]);
                        ADD2(t01, kd, rr01); ADD2(t23, kd, rr23);
                        PK2(q01, q4.x, q4.y); PK2(q23, q4.z, q4.w);
                        FMA2(a01[hh], q01, t01); FMA2(a23[hh], q23, t23);
                    }
                }
                if (dpi < 7) {
                    #pragma unroll
                    for (int hh = 0; hh < 4; hh++) kraw[hh] = nk[hh];
                }
            }
            #pragma unroll
            for (int hh = 0; hh < 4; hh++) {
                float x0, x1, x2, x3;
                UPK2(x0, x1, a01[hh]); UPK2(x2, x3, a23[hh]);
                uint2 w;
                F2TOH2(w.x, x0, x1);
                F2TOH2(w.y, x2, x3);
                sp8[((su * NHh + h0 + hh) * TK + k)] = w;
            }
        }

        // ---- stage NEXT rel block into other buffer
        if (blk + 1 < NBLK) {
            uint2* reln = relbuf + ((blk + 1) & 1) * RELB_U2;
            const long gb = (long)(kb + TK) * DHh;
            #pragma unroll
            for (int it = 0; it < 6; it++) {
                const int idx = tid + it * 384;
                if (idx < TK * DHh) {
                    const int k = idx >> 6, d = idx & 63;
                    const float* g = relg + gb + (long)k * DHh + d;
                    const float v0 = g[0];
                    const float v1 = g[QSTRIDE];
                    const float v2 = g[2 * QSTRIDE];
                    const float v3 = g[3 * QSTRIDE];
                    uint2 w;
                    F2TOH2(w.x, v0, v1);
                    F2TOH2(w.y, v2, v3);
                    reln[k * RROW + d] = w;
                }
            }
        }
        __syncthreads();

        // ---- SOFTMAX: warp = head (wid), lane = k
        {
            const int h = wid, k = lane;
            float s[TQ] = {0.f, 0.f, 0.f, 0.f};
            #pragma unroll
            for (int u = 0; u < 4; u++) {
                uint2 P = sp8[((u * NHh + h) * TK + k)];
                float e0, e1, e2, e3;
                H2TO2F(e0, e1, P.x);
                H2TO2F(e2, e3, P.y);
                s[0] += e0; s[1] += e1; s[2] += e2; s[3] += e3;
            }
            const float mv = mask[b * Ss + kb + k];
            float pr[TQ];
            #pragma unroll
            for (int qi = 0; qi < TQ; qi++) {
                s[qi] += mv;
                float mx = s[qi];
                #pragma unroll
                for (int o = 16; o; o >>= 1)
                    mx = fmaxf(mx, __shfl_xor_sync(0xffffffffu, mx, o));
                const float mnew = fmaxf(m[qi], mx);
                const float p = __expf(s[qi] - mnew);
                float ls = p;
                #pragma unroll
                for (int o = 16; o; o >>= 1)
                    ls += __shfl_xor_sync(0xffffffffu, ls, o);
                const float alpha = __expf(m[qi] - mnew);
                l[qi] = l[qi] * alpha + ls;
                m[qi] = mnew;
                pr[qi] = p;
                if (lane == 0) al_s[h * TQ + qi] = alpha;
            }
            float4 w = {pr[0], pr[1], pr[2], pr[3]};
            *(float4*)&sc[(h * TK + k) * TQ] = w;
            if (blk == NBLK - 1 && lane == 0) {
                #pragma unroll
                for (int qi = 0; qi < TQ; qi++) l_s[h * TQ + qi] = l[qi];
            }
        }
        __syncthreads();

        // ---- CTX: quad z, sub = (d-half e, k-half j), lane = d in half
        {
            const int e = su >> 1, j = su & 1;
            const int d = e * 32 + lane;
            #pragma unroll
            for (int hh = 0; hh < 4; hh++) {
                float4 al = *(const float4*)&al_s[(h0 + hh) * TQ];
                ull al01, al23;
                PK2(al01, al.x, al.y); PK2(al23, al.z, al.w);
                MUL2(c01[hh], c01[hh], al01);
                MUL2(c23[hh], c23[hh], al23);
            }
            const uint* vb = g_vh + (long)(b * (Ss / 2) + ((kb >> 1) + j * 8)) * HID + d;
            #pragma unroll
            for (int kkp = 0; kkp < 8; kkp++) {
                uint vraw[4];
                #pragma unroll
                for (int hh = 0; hh < 4; hh++)
                    vraw[hh] = vb[kkp * HID + (h0 + hh) * DHh];
                float vv[8];
                #pragma unroll
                for (int hh = 0; hh < 4; hh++)
                    H2TO2F(vv[hh * 2], vv[hh * 2 + 1], vraw[hh]);
                #pragma unroll
                for (int t = 0; t < 2; t++) {
                    const int k = j * 16 + kkp + t * 8;   // (k, k+8) half2 pairs
                    uint2 r8 = relc[k * RROW + d];
                    ull rr01, rr23;
                    H2TOF2(rr01, r8.x);
                    H2TOF2(rr23, r8.y);
                    #pragma unroll
                    for (int hh = 0; hh < 4; hh++) {
                        float4 p4 = *(const float4*)&sc[((h0 + hh) * TK + k) * TQ];
                        ull vd, u01, u23, p01, p23;
                        PK2(vd, vv[hh * 2 + t], vv[hh * 2 + t]);
                        ADD2(u01, vd, rr01); ADD2(u23, vd, rr23);
                        PK2(p01, p4.x, p4.y); PK2(p23, p4.z, p4.w);
                        FMA2(c01[hh], p01, u01); FMA2(c23[hh], p23, u23);
                    }
                }
            }
        }
        __syncthreads();
    }

    // ---- combine k-half partials and write out
    {
        const int e = su >> 1, j = su & 1;
        const int d = e * 32 + lane;
        float* cmb = (float*)sp8;          // reuse sp region
        if (j == 0) {
            #pragma unroll
            for (int hh = 0; hh < 4; hh++) {
                float x0, x1, x2, x3;
                UPK2(x0, x1, c01[hh]); UPK2(x2, x3, c23[hh]);
                float4 w = {x0, x1, x2, x3};
                *(float4*)&cmb[((h0 + hh) * DHh + d) * TQ] = w;
            }
        }
        __syncthreads();
        if (j == 1) {
            #pragma unroll
            for (int hh = 0; hh < 4; hh++) {
                float4 o = *(const float4*)&cmb[((h0 + hh) * DHh + d) * TQ];
                float x0, x1, x2, x3;
                UPK2(x0, x1, c01[hh]); UPK2(x2, x3, c23[hh]);
                const float* lv = &l_s[(h0 + hh) * TQ];
                const float r0 = (o.x + x0) / lv[0];
                const float r1 = (o.y + x1) / lv[1];
                const float r2 = (o.z + x2) / lv[2];
                const float r3 = (o.w + x3) / lv[3];
                const long base = (long)(b * Ss + q0) * HID + (h0 + hh) * DHh + d;
                out[base]           = r0;
                out[base + HID]     = r1;
                out[base + 2 * HID] = r2;
                out[base + 3 * HID] = r3;
            }
        }
    }
}

extern "C" void kernel_launch(void* const* d_in, const int* in_sizes, int n_in,
                              void* d_out, int out_size)
{
    const float* hidden = (const float*)d_in[0];
    const float* mask   = (const float*)d_in[1];
    const float* rel    = (const float*)d_in[2];
    const float* Wq     = (const float*)d_in[3];
    const float* bq     = (const float*)d_in[4];
    const float* Wk     = (const float*)d_in[5];
    const float* bk     = (const float*)d_in[6];
    const float* Wv     = (const float*)d_in[7];
    const float* bv     = (const float*)d_in[8];
    float* out = (float*)d_out;

    cudaFuncSetAttribute(attn, cudaFuncAttributeMaxDynamicSharedMemorySize, SM_BYTES);

    dim3 g(HID / 128, ROWS / 128, 3);
    qkv_gemm<<<g, 256>>>(hidden, Wq, bq, Wk, bk, Wv, bv);
    attn<<<ROWS / TQ, 384, SM_BYTES>>>(mask, rel, out);
}